// round 3
// baseline (speedup 1.0000x reference)
#include <cuda_runtime.h>
#include <math.h>

// Problem constants
#define Bn 4
#define Cch 512
#define HW 1024       // 32*32
#define HEADS 8
#define HC 64
#define Gn 4
#define GC 128
#define Npts 1024
#define RS 63

// Scratch (device globals; no allocation allowed)
__device__ float g_q [Bn*Cch*HW];
__device__ float g_xs[Bn*Cch*Npts];
__device__ float g_k [Bn*Cch*Npts];
__device__ float g_v [Bn*Cch*Npts];
__device__ float g_o [Bn*Cch*HW];
__device__ float g_pos[Bn*Gn*Npts*2];

// ---------------------------------------------------------------------------
// Generic 1x1-conv GEMM:  Y[b][o][p] = sum_i W[o][i] * X[b][i][p] + bias[o]
// O=I=512, P=1024, B=4.  64x64 tile, TK=16, 256 threads, 4x4 microtile.
// ---------------------------------------------------------------------------
__global__ __launch_bounds__(256) void gemm_pw(
    const float* __restrict__ Wm, const float* __restrict__ X,
    const float* __restrict__ bias, float* __restrict__ Y)
{
    __shared__ float Ws[16][68];
    __shared__ float Xs[16][64];
    const int b  = blockIdx.z;
    const int o0 = blockIdx.y * 64;
    const int p0 = blockIdx.x * 64;
    const int tid = threadIdx.x;
    const int tx = tid & 15, ty = tid >> 4;
    float acc[4][4];
#pragma unroll
    for (int i=0;i<4;i++)
#pragma unroll
        for (int j=0;j<4;j++) acc[i][j]=0.f;

    const float* Xb = X + (size_t)b*Cch*HW;
    for (int k0 = 0; k0 < Cch; k0 += 16) {
        {
            int o  = tid >> 2;
            int k4 = (tid & 3) * 4;
            float4 wv = *(const float4*)(Wm + (size_t)(o0+o)*Cch + k0 + k4);
            Ws[k4+0][o] = wv.x; Ws[k4+1][o] = wv.y;
            Ws[k4+2][o] = wv.z; Ws[k4+3][o] = wv.w;
        }
        {
            int k  = tid >> 4;
            int p4 = (tid & 15) * 4;
            *(float4*)&Xs[k][p4] = *(const float4*)(Xb + (size_t)(k0+k)*HW + p0 + p4);
        }
        __syncthreads();
#pragma unroll
        for (int k = 0; k < 16; k++) {
            float a[4], bb[4];
            *(float4*)a  = *(const float4*)&Ws[k][ty*4];
            *(float4*)bb = *(const float4*)&Xs[k][tx*4];
#pragma unroll
            for (int i=0;i<4;i++)
#pragma unroll
                for (int j=0;j<4;j++) acc[i][j] += a[i]*bb[j];
        }
        __syncthreads();
    }
#pragma unroll
    for (int i=0;i<4;i++){
        int o = o0 + ty*4 + i;
        float bv = bias ? bias[o] : 0.f;
#pragma unroll
        for (int j=0;j<4;j++)
            Y[(size_t)b*Cch*HW + (size_t)o*HW + p0 + tx*4 + j] = acc[i][j] + bv;
    }
}

// ---------------------------------------------------------------------------
// Offset network: depthwise 3x3 + channel LayerNorm + exact GELU + 1x1 -> 2,
// add reference grid, clip -> g_pos. Also writes pos/ref sections of d_out.
// One block (128 threads = channels) per (bg, pixel).
// ---------------------------------------------------------------------------
__global__ __launch_bounds__(128) void offset_kernel(
    const float* __restrict__ dw_w, const float* __restrict__ dw_b,
    const float* __restrict__ ln_w, const float* __restrict__ ln_b,
    const float* __restrict__ pw_w, float* __restrict__ posref, int write_pr)
{
    const int p  = blockIdx.x;       // 0..1023
    const int bg = blockIdx.y;       // 0..15
    const int ch = threadIdx.x;      // 0..127
    const int y = p >> 5, x = p & 31;
    const int b = bg >> 2, g = bg & 3;

    const float* qp = g_q + ((size_t)(b*Cch + g*GC + ch)) * HW;
    float v = dw_b[ch];
#pragma unroll
    for (int ky = 0; ky < 3; ky++){
        int yy = y + ky - 1;
        if (yy < 0 || yy > 31) continue;
#pragma unroll
        for (int kx = 0; kx < 3; kx++){
            int xx = x + kx - 1;
            if (xx < 0 || xx > 31) continue;
            v += qp[yy*32+xx] * dw_w[ch*9 + ky*3 + kx];
        }
    }
    __shared__ float red[4];
    __shared__ float red2[2][4];
    float s = v;
#pragma unroll
    for (int off=16; off; off>>=1) s += __shfl_xor_sync(0xffffffffu, s, off);
    if ((ch&31)==0) red[ch>>5] = s;
    __syncthreads();
    float mean = (red[0]+red[1]+red[2]+red[3]) * (1.f/128.f);
    __syncthreads();
    float d = v - mean;
    s = d*d;
#pragma unroll
    for (int off=16; off; off>>=1) s += __shfl_xor_sync(0xffffffffu, s, off);
    if ((ch&31)==0) red[ch>>5] = s;
    __syncthreads();
    float var = (red[0]+red[1]+red[2]+red[3]) * (1.f/128.f);
    float o = d * rsqrtf(var + 1e-5f) * ln_w[ch] + ln_b[ch];
    o = 0.5f * o * (1.f + erff(o * 0.70710678118654752440f));  // exact GELU
    float s0 = o * pw_w[ch];
    float s1 = o * pw_w[128+ch];
#pragma unroll
    for (int off=16; off; off>>=1){
        s0 += __shfl_xor_sync(0xffffffffu, s0, off);
        s1 += __shfl_xor_sync(0xffffffffu, s1, off);
    }
    if ((ch&31)==0){ red2[0][ch>>5]=s0; red2[1][ch>>5]=s1; }
    __syncthreads();
    if (ch == 0){
        float offy = red2[0][0]+red2[0][1]+red2[0][2]+red2[0][3];
        float offx = red2[1][0]+red2[1][1]+red2[1][2]+red2[1][3];
        float ry = ((y+0.5f)/31.f)*2.f - 1.f;
        float rx = ((x+0.5f)/31.f)*2.f - 1.f;
        float py = fminf(fmaxf(offy+ry, -1.f), 1.f);
        float px = fminf(fmaxf(offx+rx, -1.f), 1.f);
        int idx = (bg*Npts + p)*2;
        g_pos[idx+0] = py;
        g_pos[idx+1] = px;
        if (write_pr){
            posref[idx+0] = py;
            posref[idx+1] = px;
            posref[Bn*Gn*Npts*2 + idx + 0] = ry;
            posref[Bn*Gn*Npts*2 + idx + 1] = rx;
        }
    }
}

// ---------------------------------------------------------------------------
// Deformable bilinear sampling: xs[b][c][n] from x at g_pos.
// grid (8 channel-chunks, 16 bg); 256 threads loop n.
// ---------------------------------------------------------------------------
__global__ __launch_bounds__(256) void sample_kernel(const float* __restrict__ x)
{
    const int cc = blockIdx.x;   // 0..7 (16 channels each)
    const int bg = blockIdx.y;   // 0..15
    const int b = bg >> 2, g = bg & 3;
    for (int n = threadIdx.x; n < Npts; n += 256){
        float py = g_pos[(bg*Npts+n)*2+0];
        float px = g_pos[(bg*Npts+n)*2+1];
        float gx = (px+1.f)*0.5f*31.f;
        float gy = (py+1.f)*0.5f*31.f;
        float x0f = floorf(gx), y0f = floorf(gy);
        float wx = gx-x0f, wy = gy-y0f;
        int x0 = max(min((int)x0f, 31), 0);
        int y0 = max(min((int)y0f, 31), 0);
        int x1 = min(x0+1, 31);
        int y1 = min(y0+1, 31);
        float w00 = (1.f-wx)*(1.f-wy), w10 = wx*(1.f-wy);
        float w01 = (1.f-wx)*wy,       w11 = wx*wy;
        for (int cj = 0; cj < 16; cj++){
            int cfull = g*GC + cc*16 + cj;
            const float* pl = x + ((size_t)(b*Cch + cfull))*HW;
            float val = pl[y0*32+x0]*w00 + pl[y0*32+x1]*w10
                      + pl[y1*32+x0]*w01 + pl[y1*32+x1]*w11;
            g_xs[((size_t)(b*Cch + cfull))*Npts + n] = val;
        }
    }
}

// ---------------------------------------------------------------------------
// Fused attention with RPE bilinear bias + online softmax.
// Block = (head bh, 32-query tile). 256 threads. n-tiles of 128.
// Dyn smem: 4032+2048+4128+8256+2080+96 = 20640 floats = 80.6 KB -> 2 CTA/SM.
// ---------------------------------------------------------------------------
__global__ __launch_bounds__(256) void attn_kernel(const float* __restrict__ rpe)
{
    extern __shared__ float sm[];
    float* rpe_s = sm;               // [63][64]         4032
    float* q_s   = sm + 4032;        // [64][32] c-major 2048
    float* s_s   = q_s + 2048;       // [32][129]        4128
    float* v_s   = s_s + 4128;       // [64][129]        8256
    float* out_s = v_s + 8256;       // [32][65]         2080
    float* Mrow  = out_s + 2080;     // 32
    float* Lrow  = Mrow + 32;        // 32
    float* Arow  = Lrow + 32;        // 32

    const int tid = threadIdx.x;
    const int bh = blockIdx.y;              // 0..31
    const int m0 = blockIdx.x * 32;
    const int b = bh >> 3, h = bh & 7, g = h >> 1;
    const int lane = tid & 31, warp = tid >> 5;
    const int nn = tid & 127, mh = (tid >> 7) & 1;

    const float* rh = rpe + (size_t)h*RS*RS;
    for (int i = tid; i < RS*RS; i += 256) rpe_s[(i/RS)*64 + (i%RS)] = rh[i];

    const float* qb = g_q + ((size_t)(b*Cch + h*HC))*HW + m0;
    for (int i = tid; i < HC*32; i += 256){
        int c = i >> 5, m = i & 31;
        q_s[c*32+m] = qb[(size_t)c*HW + m];
    }
    if (tid < 32){ Mrow[tid] = -1e30f; Lrow[tid] = 0.f; }
    for (int i = tid; i < 32*HC; i += 256) out_s[(i>>6)*65 + (i&63)] = 0.f;
    __syncthreads();

    const float* kb = g_k + ((size_t)(b*Cch + h*HC))*Npts;
    const float* vb = g_v + ((size_t)(b*Cch + h*HC))*Npts;

    float qyv[16], qxv[16];
#pragma unroll
    for (int mi=0; mi<16; mi++){
        int mg = m0 + mh*16 + mi;
        qyv[mi] = (float)(mg>>5) * (2.f/31.f) - 1.f;
        qxv[mi] = (float)(mg&31) * (2.f/31.f) - 1.f;
    }

    for (int t = 0; t < Npts; t += 128){
        // V tile -> smem
        for (int i = tid; i < 64*128; i += 256){
            int c = i >> 7, n2 = i & 127;
            v_s[c*129+n2] = vb[(size_t)c*Npts + t + n2];
        }
        // scores: each thread handles n = t+nn, 16 query rows (mh half)
        float acc[16];
#pragma unroll
        for (int mi=0;mi<16;mi++) acc[mi]=0.f;
        const float* kp  = kb + t + nn;
        const float* qsp = q_s + mh*16;
#pragma unroll 8
        for (int c = 0; c < HC; c++){
            float kc = kp[(size_t)c*Npts];
#pragma unroll
            for (int mi=0;mi<16;mi++) acc[mi] += qsp[c*32+mi]*kc;
        }
        float py = g_pos[((b*Gn+g)*Npts + t + nn)*2 + 0];
        float px = g_pos[((b*Gn+g)*Npts + t + nn)*2 + 1];
#pragma unroll
        for (int mi=0;mi<16;mi++){
            float gx = ((qxv[mi]-px)*0.5f + 1.f)*31.f;
            float gy = ((qyv[mi]-py)*0.5f + 1.f)*31.f;
            float x0f = floorf(gx), y0f = floorf(gy);
            float wx = gx-x0f, wy = gy-y0f;
            int x0 = max(min((int)x0f, 62), 0);
            int y0 = max(min((int)y0f, 62), 0);
            int x1 = min(x0+1, 62);
            int y1 = min(y0+1, 62);
            float r00 = rpe_s[y0*64+x0], r01 = rpe_s[y0*64+x1];
            float r10 = rpe_s[y1*64+x0], r11 = rpe_s[y1*64+x1];
            float top = r00 + (r01-r00)*wx;
            float bot = r10 + (r11-r10)*wx;
            float bias = top + (bot-top)*wy;
            s_s[(mh*16+mi)*129 + nn] = acc[mi]*0.125f + bias;
        }
        __syncthreads();
        // online softmax: warp handles 4 rows
#pragma unroll
        for (int rr = 0; rr < 4; rr++){
            int r = warp*4 + rr;
            float mx = -1e30f;
#pragma unroll
            for (int j=0;j<4;j++) mx = fmaxf(mx, s_s[r*129 + lane + 32*j]);
#pragma unroll
            for (int off=16; off; off>>=1) mx = fmaxf(mx, __shfl_xor_sync(0xffffffffu, mx, off));
            float Mold = Mrow[r];
            float Mnew = fmaxf(Mold, mx);
            float sum = 0.f;
#pragma unroll
            for (int j=0;j<4;j++){
                float pv = __expf(s_s[r*129 + lane + 32*j] - Mnew);
                s_s[r*129 + lane + 32*j] = pv;
                sum += pv;
            }
#pragma unroll
            for (int off=16; off; off>>=1) sum += __shfl_xor_sync(0xffffffffu, sum, off);
            if (lane==0){
                float alpha = __expf(Mold - Mnew);
                Arow[r] = alpha;
                Mrow[r] = Mnew;
                Lrow[r] = Lrow[r]*alpha + sum;
            }
        }
        __syncthreads();
        // rescale running output
        for (int i = tid; i < 32*HC; i += 256){
            int m = i>>6, c = i&63;
            out_s[m*65+c] *= Arow[m];
        }
        __syncthreads();
        // P@V: 4 teams over n, each thread 4m x 8c microtile
        {
            const int team = tid >> 6;
            const int sub  = tid & 63;
            const int mg = (sub & 7) * 4;
            const int cg = (sub >> 3) * 8;
            float o[4][8];
#pragma unroll
            for (int i=0;i<4;i++)
#pragma unroll
                for (int j=0;j<8;j++) o[i][j]=0.f;
            const int nb = team*32;
#pragma unroll 4
            for (int n2 = nb; n2 < nb+32; n2++){
                float p[4], vv[8];
#pragma unroll
                for (int i=0;i<4;i++) p[i] = s_s[(mg+i)*129 + n2];
#pragma unroll
                for (int j=0;j<8;j++) vv[j] = v_s[(cg+j)*129 + n2];
#pragma unroll
                for (int i=0;i<4;i++)
#pragma unroll
                    for (int j=0;j<8;j++) o[i][j] += p[i]*vv[j];
            }
            // deterministic team-ordered accumulation
            for (int tt = 0; tt < 4; tt++){
                if (team == tt){
#pragma unroll
                    for (int i=0;i<4;i++)
#pragma unroll
                        for (int j=0;j<8;j++)
                            out_s[(mg+i)*65 + cg+j] += o[i][j];
                }
                __syncthreads();
            }
        }
    }
    // finalize (coalesced over m)
    for (int i = tid; i < 32*HC; i += 256){
        int m = i & 31, c = i >> 5;
        g_o[((size_t)(b*Cch + h*HC + c))*HW + m0 + m] = out_s[m*65+c] / Lrow[m];
    }
}

// ---------------------------------------------------------------------------
extern "C" void kernel_launch(void* const* d_in, const int* in_sizes, int n_in,
                              void* d_out, int out_size)
{
    const float* x   = (const float*)d_in[0];
    const float* wq  = (const float*)d_in[1];
    const float* bq  = (const float*)d_in[2];
    const float* wk  = (const float*)d_in[3];
    const float* bk  = (const float*)d_in[4];
    const float* wv  = (const float*)d_in[5];
    const float* bv  = (const float*)d_in[6];
    const float* wo  = (const float*)d_in[7];
    const float* bo  = (const float*)d_in[8];
    const float* dww = (const float*)d_in[9];
    const float* dwb = (const float*)d_in[10];
    const float* lnw = (const float*)d_in[11];
    const float* lnb = (const float*)d_in[12];
    const float* pww = (const float*)d_in[13];
    const float* rpe = (const float*)d_in[14];
    float* out = (float*)d_out;

    // Non-stream, capture-legal, deterministic host setup.
    void *pq, *pxs, *pk, *pv, *po;
    cudaGetSymbolAddress(&pq,  g_q);
    cudaGetSymbolAddress(&pxs, g_xs);
    cudaGetSymbolAddress(&pk,  g_k);
    cudaGetSymbolAddress(&pv,  g_v);
    cudaGetSymbolAddress(&po,  g_o);
    cudaFuncSetAttribute(attn_kernel, cudaFuncAttributeMaxDynamicSharedMemorySize,
                         20640 * (int)sizeof(float));

    const int write_pr = (out_size >= Bn*Cch*HW + 2*Bn*Gn*Npts*2) ? 1 : 0;
    float* posref = out + Bn*Cch*HW;

    const dim3 gg(HW/64, Cch/64, Bn);
    gemm_pw<<<gg, 256>>>(wq, x, bq, (float*)pq);
    offset_kernel<<<dim3(Npts, Bn*Gn), 128>>>(dww, dwb, lnw, lnb, pww, posref, write_pr);
    sample_kernel<<<dim3(8, Bn*Gn), 256>>>(x);
    gemm_pw<<<gg, 256>>>(wk, (const float*)pxs, bk, (float*)pk);
    gemm_pw<<<gg, 256>>>(wv, (const float*)pxs, bv, (float*)pv);
    attn_kernel<<<dim3(HW/32, Bn*HEADS), 256, 20640*sizeof(float)>>>(rpe);
    gemm_pw<<<gg, 256>>>(wo, (const float*)po, bo, out);
}

// round 4
// speedup vs baseline: 1.1546x; 1.1546x over previous
#include <cuda_runtime.h>
#include <math.h>

// Problem constants
#define Bn 4
#define Cch 512
#define HW 1024       // 32*32
#define HEADS 8
#define HC 64
#define Gn 4
#define GC 128
#define Npts 1024
#define RS 63

#define PADQ 68
#define PADP 65

// Scratch (device globals; no allocation allowed)
__device__ float g_q [Bn*Cch*HW];
__device__ float g_xs[Bn*Cch*Npts];
__device__ float g_k [Bn*Cch*Npts];
__device__ float g_v [Bn*Cch*Npts];
__device__ float g_o [Bn*Cch*HW];
__device__ float g_pos[Bn*Gn*Npts*2];

// ---------------------------------------------------------------------------
// 1x1-conv GEMM v2: Y[b][o][p] = sum_i W[o][i]*X[b][i][p] + bias[o]
// 128x128 tile, kc=16, 8x8 microtile, 256 threads, double-buffered smem.
// Grid (8,4,4) = 128 blocks = one wave.
// ---------------------------------------------------------------------------
__global__ __launch_bounds__(256) void gemm_pw(
    const float* __restrict__ Wm, const float* __restrict__ X,
    const float* __restrict__ bias, float* __restrict__ Y)
{
    __shared__ float Ws[2][16][132];   // [k][o]
    __shared__ float Xs[2][16][128];   // [k][p]
    const int b  = blockIdx.z;
    const int o0 = blockIdx.y * 128;
    const int p0 = blockIdx.x * 128;
    const int tid = threadIdx.x;
    const int tx = tid & 15;           // p, 8 each
    const int ty = tid >> 4;           // o, 8 each

    // load-thread mapping
    const int wo = tid & 127;          // W: o row
    const int wkg = tid >> 7;          // W: k-group 0/1 -> kk in {wkg, wkg+2}
    const int xk = tid >> 5;           // X: k row 0..7 -> kk in {xk, xk+8}
    const int xp = (tid & 31) * 4;     // X: p float4

    const float* Xb = X + (size_t)b*Cch*HW;

    float acc[8][8];
#pragma unroll
    for (int i=0;i<8;i++)
#pragma unroll
        for (int j=0;j<8;j++) acc[i][j]=0.f;

    // prologue: load chunk 0 into buffer 0
    {
        float4 w0 = *(const float4*)(Wm + (size_t)(o0+wo)*Cch + 0 + wkg*4);
        float4 w1 = *(const float4*)(Wm + (size_t)(o0+wo)*Cch + 0 + (wkg+2)*4);
        float4 x0 = *(const float4*)(Xb + (size_t)(0+xk  )*HW + p0 + xp);
        float4 x1 = *(const float4*)(Xb + (size_t)(0+xk+8)*HW + p0 + xp);
        Ws[0][wkg*4+0][wo]=w0.x; Ws[0][wkg*4+1][wo]=w0.y; Ws[0][wkg*4+2][wo]=w0.z; Ws[0][wkg*4+3][wo]=w0.w;
        Ws[0][(wkg+2)*4+0][wo]=w1.x; Ws[0][(wkg+2)*4+1][wo]=w1.y; Ws[0][(wkg+2)*4+2][wo]=w1.z; Ws[0][(wkg+2)*4+3][wo]=w1.w;
        *(float4*)&Xs[0][xk][xp]   = x0;
        *(float4*)&Xs[0][xk+8][xp] = x1;
    }
    __syncthreads();

    for (int it = 0; it < 32; it++) {
        const int cur = it & 1, nxt = cur ^ 1;
        float4 w0, w1, x0, x1;
        const bool pf = (it + 1 < 32);
        if (pf) {
            const int k0 = (it+1) * 16;
            w0 = *(const float4*)(Wm + (size_t)(o0+wo)*Cch + k0 + wkg*4);
            w1 = *(const float4*)(Wm + (size_t)(o0+wo)*Cch + k0 + (wkg+2)*4);
            x0 = *(const float4*)(Xb + (size_t)(k0+xk  )*HW + p0 + xp);
            x1 = *(const float4*)(Xb + (size_t)(k0+xk+8)*HW + p0 + xp);
        }
#pragma unroll
        for (int k = 0; k < 16; k++) {
            float a[8], bb[8];
            *(float4*)&a[0]  = *(const float4*)&Ws[cur][k][ty*8];
            *(float4*)&a[4]  = *(const float4*)&Ws[cur][k][ty*8+4];
            *(float4*)&bb[0] = *(const float4*)&Xs[cur][k][tx*8];
            *(float4*)&bb[4] = *(const float4*)&Xs[cur][k][tx*8+4];
#pragma unroll
            for (int i=0;i<8;i++)
#pragma unroll
                for (int j=0;j<8;j++) acc[i][j] += a[i]*bb[j];
        }
        if (pf) {
            Ws[nxt][wkg*4+0][wo]=w0.x; Ws[nxt][wkg*4+1][wo]=w0.y; Ws[nxt][wkg*4+2][wo]=w0.z; Ws[nxt][wkg*4+3][wo]=w0.w;
            Ws[nxt][(wkg+2)*4+0][wo]=w1.x; Ws[nxt][(wkg+2)*4+1][wo]=w1.y; Ws[nxt][(wkg+2)*4+2][wo]=w1.z; Ws[nxt][(wkg+2)*4+3][wo]=w1.w;
            *(float4*)&Xs[nxt][xk][xp]   = x0;
            *(float4*)&Xs[nxt][xk+8][xp] = x1;
        }
        __syncthreads();
    }

#pragma unroll
    for (int i=0;i<8;i++){
        const int o = o0 + ty*8 + i;
        const float bv = bias ? bias[o] : 0.f;
        float4 r0, r1;
        r0.x=acc[i][0]+bv; r0.y=acc[i][1]+bv; r0.z=acc[i][2]+bv; r0.w=acc[i][3]+bv;
        r1.x=acc[i][4]+bv; r1.y=acc[i][5]+bv; r1.z=acc[i][6]+bv; r1.w=acc[i][7]+bv;
        *(float4*)(Y + (size_t)b*Cch*HW + (size_t)o*HW + p0 + tx*8)     = r0;
        *(float4*)(Y + (size_t)b*Cch*HW + (size_t)o*HW + p0 + tx*8 + 4) = r1;
    }
}

// ---------------------------------------------------------------------------
// Offset network: depthwise 3x3 + channel LayerNorm + exact GELU + 1x1 -> 2,
// add reference grid, clip -> g_pos. Also writes pos/ref sections of d_out.
// ---------------------------------------------------------------------------
__global__ __launch_bounds__(128) void offset_kernel(
    const float* __restrict__ dw_w, const float* __restrict__ dw_b,
    const float* __restrict__ ln_w, const float* __restrict__ ln_b,
    const float* __restrict__ pw_w, float* __restrict__ posref, int write_pr)
{
    const int p  = blockIdx.x;       // 0..1023
    const int bg = blockIdx.y;       // 0..15
    const int ch = threadIdx.x;      // 0..127
    const int y = p >> 5, x = p & 31;
    const int b = bg >> 2, g = bg & 3;

    const float* qp = g_q + ((size_t)(b*Cch + g*GC + ch)) * HW;
    float v = dw_b[ch];
#pragma unroll
    for (int ky = 0; ky < 3; ky++){
        int yy = y + ky - 1;
        if (yy < 0 || yy > 31) continue;
#pragma unroll
        for (int kx = 0; kx < 3; kx++){
            int xx = x + kx - 1;
            if (xx < 0 || xx > 31) continue;
            v += qp[yy*32+xx] * dw_w[ch*9 + ky*3 + kx];
        }
    }
    __shared__ float red[4];
    __shared__ float red2[2][4];
    float s = v;
#pragma unroll
    for (int off=16; off; off>>=1) s += __shfl_xor_sync(0xffffffffu, s, off);
    if ((ch&31)==0) red[ch>>5] = s;
    __syncthreads();
    float mean = (red[0]+red[1]+red[2]+red[3]) * (1.f/128.f);
    __syncthreads();
    float d = v - mean;
    s = d*d;
#pragma unroll
    for (int off=16; off; off>>=1) s += __shfl_xor_sync(0xffffffffu, s, off);
    if ((ch&31)==0) red[ch>>5] = s;
    __syncthreads();
    float var = (red[0]+red[1]+red[2]+red[3]) * (1.f/128.f);
    float o = d * rsqrtf(var + 1e-5f) * ln_w[ch] + ln_b[ch];
    o = 0.5f * o * (1.f + erff(o * 0.70710678118654752440f));  // exact GELU
    float s0 = o * pw_w[ch];
    float s1 = o * pw_w[128+ch];
#pragma unroll
    for (int off=16; off; off>>=1){
        s0 += __shfl_xor_sync(0xffffffffu, s0, off);
        s1 += __shfl_xor_sync(0xffffffffu, s1, off);
    }
    if ((ch&31)==0){ red2[0][ch>>5]=s0; red2[1][ch>>5]=s1; }
    __syncthreads();
    if (ch == 0){
        float offy = red2[0][0]+red2[0][1]+red2[0][2]+red2[0][3];
        float offx = red2[1][0]+red2[1][1]+red2[1][2]+red2[1][3];
        float ry = ((y+0.5f)/31.f)*2.f - 1.f;
        float rx = ((x+0.5f)/31.f)*2.f - 1.f;
        float py = fminf(fmaxf(offy+ry, -1.f), 1.f);
        float px = fminf(fmaxf(offx+rx, -1.f), 1.f);
        int idx = (bg*Npts + p)*2;
        g_pos[idx+0] = py;
        g_pos[idx+1] = px;
        if (write_pr){
            posref[idx+0] = py;
            posref[idx+1] = px;
            posref[Bn*Gn*Npts*2 + idx + 0] = ry;
            posref[Bn*Gn*Npts*2 + idx + 1] = rx;
        }
    }
}

// ---------------------------------------------------------------------------
// Deformable bilinear sampling: xs[b][c][n] from x at g_pos.
// ---------------------------------------------------------------------------
__global__ __launch_bounds__(256) void sample_kernel(const float* __restrict__ x)
{
    const int cc = blockIdx.x;   // 0..7 (16 channels each)
    const int bg = blockIdx.y;   // 0..15
    const int b = bg >> 2, g = bg & 3;
    for (int n = threadIdx.x; n < Npts; n += 256){
        float py = g_pos[(bg*Npts+n)*2+0];
        float px = g_pos[(bg*Npts+n)*2+1];
        float gx = (px+1.f)*0.5f*31.f;
        float gy = (py+1.f)*0.5f*31.f;
        float x0f = floorf(gx), y0f = floorf(gy);
        float wx = gx-x0f, wy = gy-y0f;
        int x0 = max(min((int)x0f, 31), 0);
        int y0 = max(min((int)y0f, 31), 0);
        int x1 = min(x0+1, 31);
        int y1 = min(y0+1, 31);
        float w00 = (1.f-wx)*(1.f-wy), w10 = wx*(1.f-wy);
        float w01 = (1.f-wx)*wy,       w11 = wx*wy;
        for (int cj = 0; cj < 16; cj++){
            int cfull = g*GC + cc*16 + cj;
            const float* pl = x + ((size_t)(b*Cch + cfull))*HW;
            float val = pl[y0*32+x0]*w00 + pl[y0*32+x1]*w10
                      + pl[y1*32+x0]*w01 + pl[y1*32+x1]*w11;
            g_xs[((size_t)(b*Cch + cfull))*Npts + n] = val;
        }
    }
}

// ---------------------------------------------------------------------------
// Fused attention v2: m-tile 64, n-tile 64, 256 threads (16x16 grid),
// 4x4 register microtiles for QK and PV, PV accumulator in registers,
// online softmax, RPE bias bilinear from smem.
// Dyn smem: 4032+4352+4352+4160+4160+5*64 = 21376 floats = 85.5 KB.
// ---------------------------------------------------------------------------
__global__ __launch_bounds__(256) void attn_kernel(const float* __restrict__ rpe)
{
    extern __shared__ float sm[];
    float* rpe_s = sm;                 // [63][64]       4032
    float* q_s   = rpe_s + 4032;       // [64][PADQ]     4352  (c-major, m cols)
    float* k_s   = q_s + 4352;         // [64][PADQ]     4352  (c-major, n cols)
    float* v_s   = k_s + 4352;         // [64][PADP]     4160  (c-major, n cols)
    float* p_s   = v_s + 4160;         // [64][PADP]     4160  (m-major, n cols)
    float* py_s  = p_s + 4160;         // 64
    float* px_s  = py_s + 64;          // 64
    float* Mrow  = px_s + 64;          // 64
    float* Lrow  = Mrow + 64;          // 64
    float* Arow  = Lrow + 64;          // 64

    const int tid = threadIdx.x;
    const int bh = blockIdx.y;              // 0..31
    const int m0 = blockIdx.x * 64;
    const int b = bh >> 3, h = bh & 7, g = h >> 1;
    const int lane = tid & 31, warp = tid >> 5;
    const int tx = tid & 15;                // n, 4 each
    const int ty = tid >> 4;                // m, 4 each
    const int bg = b*Gn + g;

    const float* rh = rpe + (size_t)h*RS*RS;
    for (int i = tid; i < RS*RS; i += 256) rpe_s[(i/RS)*64 + (i%RS)] = rh[i];

    const float* qb = g_q + ((size_t)(b*Cch + h*HC))*HW + m0;
    for (int i = tid; i < 64*64; i += 256){
        int c = i >> 6, m = i & 63;
        q_s[c*PADQ + m] = qb[(size_t)c*HW + m];
    }
    if (tid < 64){ Mrow[tid] = -1e30f; Lrow[tid] = 0.f; }

    float out[4][4];
#pragma unroll
    for (int i=0;i<4;i++)
#pragma unroll
        for (int j=0;j<4;j++) out[i][j]=0.f;

    float qy[4], qx[4];
#pragma unroll
    for (int i=0;i<4;i++){
        int mg = m0 + ty*4 + i;
        qy[i] = (float)(mg>>5) * (2.f/31.f) - 1.f;
        qx[i] = (float)(mg&31) * (2.f/31.f) - 1.f;
    }

    const float* kb = g_k + ((size_t)(b*Cch + h*HC))*Npts;
    const float* vb = g_v + ((size_t)(b*Cch + h*HC))*Npts;

    __syncthreads();

    for (int t = 0; t < Npts; t += 64){
        // K,V tiles + pos -> smem
        for (int i = tid; i < 64*64; i += 256){
            int c = i >> 6, n = i & 63;
            k_s[c*PADQ + n] = kb[(size_t)c*Npts + t + n];
            v_s[c*PADP + n] = vb[(size_t)c*Npts + t + n];
        }
        if (tid < 64){
            py_s[tid] = g_pos[((size_t)bg*Npts + t + tid)*2 + 0];
            px_s[tid] = g_pos[((size_t)bg*Npts + t + tid)*2 + 1];
        }
        __syncthreads();

        // QK 4x4 microtile
        float s4[4][4];
#pragma unroll
        for (int i=0;i<4;i++)
#pragma unroll
            for (int j=0;j<4;j++) s4[i][j]=0.f;
#pragma unroll 8
        for (int c = 0; c < HC; c++){
            float a[4], bb[4];
            *(float4*)a  = *(const float4*)&q_s[c*PADQ + ty*4];
            *(float4*)bb = *(const float4*)&k_s[c*PADQ + tx*4];
#pragma unroll
            for (int i=0;i<4;i++)
#pragma unroll
                for (int j=0;j<4;j++) s4[i][j] += a[i]*bb[j];
        }
        // RPE bias + store scores
#pragma unroll
        for (int j=0;j<4;j++){
            int n = tx*4 + j;
            float py = py_s[n], px = px_s[n];
#pragma unroll
            for (int i=0;i<4;i++){
                float gx = ((qx[i]-px)*0.5f + 1.f)*31.f;
                float gy = ((qy[i]-py)*0.5f + 1.f)*31.f;
                float x0f = floorf(gx), y0f = floorf(gy);
                float wx = gx-x0f, wy = gy-y0f;
                int x0 = max(min((int)x0f, 62), 0);
                int y0 = max(min((int)y0f, 62), 0);
                int x1 = min(x0+1, 62);
                int y1 = min(y0+1, 62);
                float r00 = rpe_s[y0*64+x0], r01 = rpe_s[y0*64+x1];
                float r10 = rpe_s[y1*64+x0], r11 = rpe_s[y1*64+x1];
                float top = r00 + (r01-r00)*wx;
                float bot = r10 + (r11-r10)*wx;
                float bias = top + (bot-top)*wy;
                p_s[(ty*4+i)*PADP + n] = s4[i][j]*0.125f + bias;
            }
        }
        __syncthreads();

        // online softmax: warp handles 8 rows
#pragma unroll
        for (int rr = 0; rr < 8; rr++){
            int r = warp*8 + rr;
            float v0 = p_s[r*PADP + lane];
            float v1 = p_s[r*PADP + 32 + lane];
            float mx = fmaxf(v0, v1);
#pragma unroll
            for (int off=16; off; off>>=1) mx = fmaxf(mx, __shfl_xor_sync(0xffffffffu, mx, off));
            float Mold = Mrow[r];
            float Mnew = fmaxf(Mold, mx);
            float e0 = __expf(v0 - Mnew);
            float e1 = __expf(v1 - Mnew);
            p_s[r*PADP + lane] = e0;
            p_s[r*PADP + 32 + lane] = e1;
            float sum = e0 + e1;
#pragma unroll
            for (int off=16; off; off>>=1) sum += __shfl_xor_sync(0xffffffffu, sum, off);
            if (lane==0){
                float alpha = __expf(Mold - Mnew);
                Arow[r] = alpha;
                Mrow[r] = Mnew;
                Lrow[r] = Lrow[r]*alpha + sum;
            }
        }
        __syncthreads();

        // rescale register accumulator + PV
        {
            float al[4];
#pragma unroll
            for (int i=0;i<4;i++) al[i] = Arow[ty*4+i];
#pragma unroll
            for (int i=0;i<4;i++)
#pragma unroll
                for (int j=0;j<4;j++) out[i][j] *= al[i];
        }
#pragma unroll 4
        for (int n = 0; n < 64; n++){
            float pr[4], vr[4];
#pragma unroll
            for (int i=0;i<4;i++) pr[i] = p_s[(ty*4+i)*PADP + n];
#pragma unroll
            for (int j=0;j<4;j++) vr[j] = v_s[(tx*4+j)*PADP + n];
#pragma unroll
            for (int i=0;i<4;i++)
#pragma unroll
                for (int j=0;j<4;j++) out[i][j] += pr[i]*vr[j];
        }
        __syncthreads();   // before k_s/v_s/p_s overwrite next iter
    }

    // finalize: stage [c][m] in p_s then coalesced store
    {
        float li[4];
#pragma unroll
        for (int i=0;i<4;i++) li[i] = 1.f / Lrow[ty*4+i];
#pragma unroll
        for (int i=0;i<4;i++)
#pragma unroll
            for (int j=0;j<4;j++)
                p_s[(tx*4+j)*PADP + ty*4+i] = out[i][j]*li[i];
    }
    __syncthreads();
    for (int i = tid; i < 64*64; i += 256){
        int c = i >> 6, m = i & 63;
        g_o[((size_t)(b*Cch + h*HC + c))*HW + m0 + m] = p_s[c*PADP + m];
    }
}

// ---------------------------------------------------------------------------
extern "C" void kernel_launch(void* const* d_in, const int* in_sizes, int n_in,
                              void* d_out, int out_size)
{
    const float* x   = (const float*)d_in[0];
    const float* wq  = (const float*)d_in[1];
    const float* bq  = (const float*)d_in[2];
    const float* wk  = (const float*)d_in[3];
    const float* bk  = (const float*)d_in[4];
    const float* wv  = (const float*)d_in[5];
    const float* bv  = (const float*)d_in[6];
    const float* wo  = (const float*)d_in[7];
    const float* bo  = (const float*)d_in[8];
    const float* dww = (const float*)d_in[9];
    const float* dwb = (const float*)d_in[10];
    const float* lnw = (const float*)d_in[11];
    const float* lnb = (const float*)d_in[12];
    const float* pww = (const float*)d_in[13];
    const float* rpe = (const float*)d_in[14];
    float* out = (float*)d_out;

    void *pq, *pxs, *pk, *pv, *po;
    cudaGetSymbolAddress(&pq,  g_q);
    cudaGetSymbolAddress(&pxs, g_xs);
    cudaGetSymbolAddress(&pk,  g_k);
    cudaGetSymbolAddress(&pv,  g_v);
    cudaGetSymbolAddress(&po,  g_o);
    cudaFuncSetAttribute(attn_kernel, cudaFuncAttributeMaxDynamicSharedMemorySize,
                         21376 * (int)sizeof(float));

    const int write_pr = (out_size >= Bn*Cch*HW + 2*Bn*Gn*Npts*2) ? 1 : 0;
    float* posref = out + Bn*Cch*HW;

    const dim3 gg(HW/128, Cch/128, Bn);
    gemm_pw<<<gg, 256>>>(wq, x, bq, (float*)pq);
    offset_kernel<<<dim3(Npts, Bn*Gn), 128>>>(dww, dwb, lnw, lnb, pww, posref, write_pr);
    sample_kernel<<<dim3(8, Bn*Gn), 256>>>(x);
    gemm_pw<<<gg, 256>>>(wk, (const float*)pxs, bk, (float*)pk);
    gemm_pw<<<gg, 256>>>(wv, (const float*)pxs, bv, (float*)pv);
    attn_kernel<<<dim3(HW/64, Bn*HEADS), 256, 21376*sizeof(float)>>>(rpe);
    gemm_pw<<<gg, 256>>>(wo, (const float*)po, bo, out);
}

// round 5
// speedup vs baseline: 1.1613x; 1.0058x over previous
#include <cuda_runtime.h>
#include <math.h>

// Problem constants
#define Bn 4
#define Cch 512
#define HW 1024       // 32*32
#define HEADS 8
#define HC 64
#define Gn 4
#define GC 128
#define Npts 1024
#define RS 63

#define PADQ 68
#define PADP 68

// Scratch (device globals; no allocation allowed)
__device__ float g_q [Bn*Cch*HW];
__device__ float g_xs[Bn*Cch*Npts];
__device__ float g_k [Bn*Cch*Npts];
__device__ float g_v [Bn*Cch*Npts];
__device__ float g_o [Bn*Cch*HW];
__device__ float g_pos[Bn*Gn*Npts*2];

// v_s chunk swizzle: logical column n of channel c stored at n ^ vxor(c)
__device__ __forceinline__ int vxor(int c){ return ((c>>3)&7)<<2; }

// ---------------------------------------------------------------------------
// 1x1-conv GEMM: Y[b][o][p] = sum_i W[o][i]*X[b][i][p] + bias[o]
// 128x128 tile, kc=16, 8x8 microtile, 256 threads, double-buffered smem.
// ---------------------------------------------------------------------------
__device__ __forceinline__ void gemm_body(
    const float* __restrict__ Wm, const float* __restrict__ X,
    const float* __restrict__ bias, float* __restrict__ Y,
    int b, int o0, int p0, int tid,
    float (*Ws)[16][132], float (*Xs)[16][128])
{
    const int tx = tid & 15;           // p, 8 each
    const int ty = tid >> 4;           // o, 8 each
    const int wo = tid & 127;
    const int wkg = tid >> 7;
    const int xk = tid >> 5;
    const int xp = (tid & 31) * 4;

    const float* Xb = X + (size_t)b*Cch*HW;

    float acc[8][8];
#pragma unroll
    for (int i=0;i<8;i++)
#pragma unroll
        for (int j=0;j<8;j++) acc[i][j]=0.f;

    {
        float4 w0 = *(const float4*)(Wm + (size_t)(o0+wo)*Cch + 0 + wkg*4);
        float4 w1 = *(const float4*)(Wm + (size_t)(o0+wo)*Cch + 0 + (wkg+2)*4);
        float4 x0 = *(const float4*)(Xb + (size_t)(0+xk  )*HW + p0 + xp);
        float4 x1 = *(const float4*)(Xb + (size_t)(0+xk+8)*HW + p0 + xp);
        Ws[0][wkg*4+0][wo]=w0.x; Ws[0][wkg*4+1][wo]=w0.y; Ws[0][wkg*4+2][wo]=w0.z; Ws[0][wkg*4+3][wo]=w0.w;
        Ws[0][(wkg+2)*4+0][wo]=w1.x; Ws[0][(wkg+2)*4+1][wo]=w1.y; Ws[0][(wkg+2)*4+2][wo]=w1.z; Ws[0][(wkg+2)*4+3][wo]=w1.w;
        *(float4*)&Xs[0][xk][xp]   = x0;
        *(float4*)&Xs[0][xk+8][xp] = x1;
    }
    __syncthreads();

    for (int it = 0; it < 32; it++) {
        const int cur = it & 1, nxt = cur ^ 1;
        float4 w0, w1, x0, x1;
        const bool pf = (it + 1 < 32);
        if (pf) {
            const int k0 = (it+1) * 16;
            w0 = *(const float4*)(Wm + (size_t)(o0+wo)*Cch + k0 + wkg*4);
            w1 = *(const float4*)(Wm + (size_t)(o0+wo)*Cch + k0 + (wkg+2)*4);
            x0 = *(const float4*)(Xb + (size_t)(k0+xk  )*HW + p0 + xp);
            x1 = *(const float4*)(Xb + (size_t)(k0+xk+8)*HW + p0 + xp);
        }
#pragma unroll
        for (int k = 0; k < 16; k++) {
            float a[8], bb[8];
            *(float4*)&a[0]  = *(const float4*)&Ws[cur][k][ty*8];
            *(float4*)&a[4]  = *(const float4*)&Ws[cur][k][ty*8+4];
            *(float4*)&bb[0] = *(const float4*)&Xs[cur][k][tx*8];
            *(float4*)&bb[4] = *(const float4*)&Xs[cur][k][tx*8+4];
#pragma unroll
            for (int i=0;i<8;i++)
#pragma unroll
                for (int j=0;j<8;j++) acc[i][j] += a[i]*bb[j];
        }
        if (pf) {
            Ws[nxt][wkg*4+0][wo]=w0.x; Ws[nxt][wkg*4+1][wo]=w0.y; Ws[nxt][wkg*4+2][wo]=w0.z; Ws[nxt][wkg*4+3][wo]=w0.w;
            Ws[nxt][(wkg+2)*4+0][wo]=w1.x; Ws[nxt][(wkg+2)*4+1][wo]=w1.y; Ws[nxt][(wkg+2)*4+2][wo]=w1.z; Ws[nxt][(wkg+2)*4+3][wo]=w1.w;
            *(float4*)&Xs[nxt][xk][xp]   = x0;
            *(float4*)&Xs[nxt][xk+8][xp] = x1;
        }
        __syncthreads();
    }

#pragma unroll
    for (int i=0;i<8;i++){
        const int o = o0 + ty*8 + i;
        const float bv = bias ? bias[o] : 0.f;
        float4 r0, r1;
        r0.x=acc[i][0]+bv; r0.y=acc[i][1]+bv; r0.z=acc[i][2]+bv; r0.w=acc[i][3]+bv;
        r1.x=acc[i][4]+bv; r1.y=acc[i][5]+bv; r1.z=acc[i][6]+bv; r1.w=acc[i][7]+bv;
        *(float4*)(Y + (size_t)b*Cch*HW + (size_t)o*HW + p0 + tx*8)     = r0;
        *(float4*)(Y + (size_t)b*Cch*HW + (size_t)o*HW + p0 + tx*8 + 4) = r1;
    }
}

__global__ __launch_bounds__(256) void gemm_pw(
    const float* __restrict__ Wm, const float* __restrict__ X,
    const float* __restrict__ bias, float* __restrict__ Y)
{
    __shared__ float Ws[2][16][132];
    __shared__ float Xs[2][16][128];
    gemm_body(Wm, X, bias, Y, blockIdx.z, blockIdx.y*128, blockIdx.x*128,
              threadIdx.x, Ws, Xs);
}

// Fused K+V GEMM: blockIdx.y in [0,8): first 4 -> K, last 4 -> V.
__global__ __launch_bounds__(256) void gemm_kv(
    const float* __restrict__ wk, const float* __restrict__ bk, float* __restrict__ Yk,
    const float* __restrict__ wv, const float* __restrict__ bv, float* __restrict__ Yv,
    const float* __restrict__ X)
{
    __shared__ float Ws[2][16][132];
    __shared__ float Xs[2][16][128];
    const int y = blockIdx.y;
    if (y < 4)
        gemm_body(wk, X, bk, Yk, blockIdx.z, y*128, blockIdx.x*128, threadIdx.x, Ws, Xs);
    else
        gemm_body(wv, X, bv, Yv, blockIdx.z, (y-4)*128, blockIdx.x*128, threadIdx.x, Ws, Xs);
}

// ---------------------------------------------------------------------------
// Offset network: depthwise 3x3 + channel LayerNorm + exact GELU + 1x1 -> 2.
// ---------------------------------------------------------------------------
__global__ __launch_bounds__(128) void offset_kernel(
    const float* __restrict__ dw_w, const float* __restrict__ dw_b,
    const float* __restrict__ ln_w, const float* __restrict__ ln_b,
    const float* __restrict__ pw_w, float* __restrict__ posref, int write_pr)
{
    const int p  = blockIdx.x;       // 0..1023
    const int bg = blockIdx.y;       // 0..15
    const int ch = threadIdx.x;      // 0..127
    const int y = p >> 5, x = p & 31;
    const int b = bg >> 2, g = bg & 3;

    const float* qp = g_q + ((size_t)(b*Cch + g*GC + ch)) * HW;
    float v = dw_b[ch];
#pragma unroll
    for (int ky = 0; ky < 3; ky++){
        int yy = y + ky - 1;
        if (yy < 0 || yy > 31) continue;
#pragma unroll
        for (int kx = 0; kx < 3; kx++){
            int xx = x + kx - 1;
            if (xx < 0 || xx > 31) continue;
            v += qp[yy*32+xx] * dw_w[ch*9 + ky*3 + kx];
        }
    }
    __shared__ float red[4];
    __shared__ float red2[2][4];
    float s = v;
#pragma unroll
    for (int off=16; off; off>>=1) s += __shfl_xor_sync(0xffffffffu, s, off);
    if ((ch&31)==0) red[ch>>5] = s;
    __syncthreads();
    float mean = (red[0]+red[1]+red[2]+red[3]) * (1.f/128.f);
    __syncthreads();
    float d = v - mean;
    s = d*d;
#pragma unroll
    for (int off=16; off; off>>=1) s += __shfl_xor_sync(0xffffffffu, s, off);
    if ((ch&31)==0) red[ch>>5] = s;
    __syncthreads();
    float var = (red[0]+red[1]+red[2]+red[3]) * (1.f/128.f);
    float o = d * rsqrtf(var + 1e-5f) * ln_w[ch] + ln_b[ch];
    o = 0.5f * o * (1.f + erff(o * 0.70710678118654752440f));  // exact GELU
    float s0 = o * pw_w[ch];
    float s1 = o * pw_w[128+ch];
#pragma unroll
    for (int off=16; off; off>>=1){
        s0 += __shfl_xor_sync(0xffffffffu, s0, off);
        s1 += __shfl_xor_sync(0xffffffffu, s1, off);
    }
    if ((ch&31)==0){ red2[0][ch>>5]=s0; red2[1][ch>>5]=s1; }
    __syncthreads();
    if (ch == 0){
        float offy = red2[0][0]+red2[0][1]+red2[0][2]+red2[0][3];
        float offx = red2[1][0]+red2[1][1]+red2[1][2]+red2[1][3];
        float ry = ((y+0.5f)/31.f)*2.f - 1.f;
        float rx = ((x+0.5f)/31.f)*2.f - 1.f;
        float py = fminf(fmaxf(offy+ry, -1.f), 1.f);
        float px = fminf(fmaxf(offx+rx, -1.f), 1.f);
        int idx = (bg*Npts + p)*2;
        g_pos[idx+0] = py;
        g_pos[idx+1] = px;
        if (write_pr){
            posref[idx+0] = py;
            posref[idx+1] = px;
            posref[Bn*Gn*Npts*2 + idx + 0] = ry;
            posref[Bn*Gn*Npts*2 + idx + 1] = rx;
        }
    }
}

// ---------------------------------------------------------------------------
// Deformable bilinear sampling: xs[b][c][n] from x at g_pos.
// ---------------------------------------------------------------------------
__global__ __launch_bounds__(256) void sample_kernel(const float* __restrict__ x)
{
    const int cc = blockIdx.x;   // 0..7 (16 channels each)
    const int bg = blockIdx.y;   // 0..15
    const int b = bg >> 2, g = bg & 3;
    for (int n = threadIdx.x; n < Npts; n += 256){
        float py = g_pos[(bg*Npts+n)*2+0];
        float px = g_pos[(bg*Npts+n)*2+1];
        float gx = (px+1.f)*0.5f*31.f;
        float gy = (py+1.f)*0.5f*31.f;
        float x0f = floorf(gx), y0f = floorf(gy);
        float wx = gx-x0f, wy = gy-y0f;
        int x0 = max(min((int)x0f, 31), 0);
        int y0 = max(min((int)y0f, 31), 0);
        int x1 = min(x0+1, 31);
        int y1 = min(y0+1, 31);
        float w00 = (1.f-wx)*(1.f-wy), w10 = wx*(1.f-wy);
        float w01 = (1.f-wx)*wy,       w11 = wx*wy;
        for (int cj = 0; cj < 16; cj++){
            int cfull = g*GC + cc*16 + cj;
            const float* pl = x + ((size_t)(b*Cch + cfull))*HW;
            float val = pl[y0*32+x0]*w00 + pl[y0*32+x1]*w10
                      + pl[y1*32+x0]*w01 + pl[y1*32+x1]*w11;
            g_xs[((size_t)(b*Cch + cfull))*Npts + n] = val;
        }
    }
}

// ---------------------------------------------------------------------------
// Fused attention v3: m-tile 64, n-tile 64, 256 threads (16x16), 4x4
// microtiles, vectorized PV via swizzled v_s, float4 score stores.
// Dyn smem: 4032 + 4*4352 + 5*64 = 21760 floats = 87,040 B -> 2 CTA/SM.
// ---------------------------------------------------------------------------
__global__ __launch_bounds__(256) void attn_kernel(const float* __restrict__ rpe)
{
    extern __shared__ float sm[];
    float* rpe_s = sm;                 // [63][64]       4032
    float* q_s   = rpe_s + 4032;       // [64][PADQ]     4352  (c-major, m cols)
    float* k_s   = q_s + 4352;         // [64][PADQ]     4352  (c-major, n cols)
    float* v_s   = k_s + 4352;         // [64][PADP]     4352  (c-major, n swizzled)
    float* p_s   = v_s + 4352;         // [64][PADP]     4352  (m-major, n cols)
    float* py_s  = p_s + 4352;         // 64
    float* px_s  = py_s + 64;          // 64
    float* Mrow  = px_s + 64;          // 64
    float* Lrow  = Mrow + 64;          // 64
    float* Arow  = Lrow + 64;          // 64

    const int tid = threadIdx.x;
    const int bh = blockIdx.y;              // 0..31
    const int m0 = blockIdx.x * 64;
    const int b = bh >> 3, h = bh & 7, g = h >> 1;
    const int lane = tid & 31, warp = tid >> 5;
    const int tx = tid & 15;                // n, 4 each
    const int ty = tid >> 4;                // m, 4 each
    const int bg = b*Gn + g;

    const float* rh = rpe + (size_t)h*RS*RS;
    for (int i = tid; i < RS*RS; i += 256) rpe_s[(i/RS)*64 + (i%RS)] = rh[i];

    const float* qb = g_q + ((size_t)(b*Cch + h*HC))*HW + m0;
    for (int i = tid; i < 64*64; i += 256){
        int c = i >> 6, m = i & 63;
        q_s[c*PADQ + m] = qb[(size_t)c*HW + m];
    }
    if (tid < 64){ Mrow[tid] = -1e30f; Lrow[tid] = 0.f; }

    float out[4][4];
#pragma unroll
    for (int i=0;i<4;i++)
#pragma unroll
        for (int j=0;j<4;j++) out[i][j]=0.f;

    float qy[4], qx[4];
#pragma unroll
    for (int i=0;i<4;i++){
        int mg = m0 + ty*4 + i;
        qy[i] = (float)(mg>>5) * (2.f/31.f) - 1.f;
        qx[i] = (float)(mg&31) * (2.f/31.f) - 1.f;
    }

    const float* kb = g_k + ((size_t)(b*Cch + h*HC))*Npts;
    const float* vb = g_v + ((size_t)(b*Cch + h*HC))*Npts;

    __syncthreads();

    for (int t = 0; t < Npts; t += 64){
        // K,V tiles + pos -> smem (v swizzled by 16B chunk)
        for (int i = tid; i < 64*64; i += 256){
            int c = i >> 6, n = i & 63;
            k_s[c*PADQ + n] = kb[(size_t)c*Npts + t + n];
            v_s[c*PADP + (n ^ vxor(c))] = vb[(size_t)c*Npts + t + n];
        }
        if (tid < 64){
            py_s[tid] = g_pos[((size_t)bg*Npts + t + tid)*2 + 0];
            px_s[tid] = g_pos[((size_t)bg*Npts + t + tid)*2 + 1];
        }
        __syncthreads();

        // QK 4x4 microtile
        float s4[4][4];
#pragma unroll
        for (int i=0;i<4;i++)
#pragma unroll
            for (int j=0;j<4;j++) s4[i][j]=0.f;
#pragma unroll 8
        for (int c = 0; c < HC; c++){
            float a[4], bb[4];
            *(float4*)a  = *(const float4*)&q_s[c*PADQ + ty*4];
            *(float4*)bb = *(const float4*)&k_s[c*PADQ + tx*4];
#pragma unroll
            for (int i=0;i<4;i++)
#pragma unroll
                for (int j=0;j<4;j++) s4[i][j] += a[i]*bb[j];
        }
        // RPE bias folded into register tile, then float4 stores
#pragma unroll
        for (int j=0;j<4;j++){
            int n = tx*4 + j;
            float py = py_s[n], px = px_s[n];
#pragma unroll
            for (int i=0;i<4;i++){
                float gx = ((qx[i]-px)*0.5f + 1.f)*31.f;
                float gy = ((qy[i]-py)*0.5f + 1.f)*31.f;
                float x0f = floorf(gx), y0f = floorf(gy);
                float wx = gx-x0f, wy = gy-y0f;
                int x0 = max(min((int)x0f, 62), 0);
                int y0 = max(min((int)y0f, 62), 0);
                int x1 = min(x0+1, 62);
                int y1 = min(y0+1, 62);
                float r00 = rpe_s[y0*64+x0], r01 = rpe_s[y0*64+x1];
                float r10 = rpe_s[y1*64+x0], r11 = rpe_s[y1*64+x1];
                float top = r00 + (r01-r00)*wx;
                float bot = r10 + (r11-r10)*wx;
                float bias = top + (bot-top)*wy;
                s4[i][j] = s4[i][j]*0.125f + bias;
            }
        }
#pragma unroll
        for (int i=0;i<4;i++)
            *(float4*)&p_s[(ty*4+i)*PADP + tx*4] = *(float4*)&s4[i][0];
        __syncthreads();

        // online softmax: warp handles 8 rows
#pragma unroll
        for (int rr = 0; rr < 8; rr++){
            int r = warp*8 + rr;
            float v0 = p_s[r*PADP + lane];
            float v1 = p_s[r*PADP + 32 + lane];
            float mx = fmaxf(v0, v1);
#pragma unroll
            for (int off=16; off; off>>=1) mx = fmaxf(mx, __shfl_xor_sync(0xffffffffu, mx, off));
            float Mold = Mrow[r];
            float Mnew = fmaxf(Mold, mx);
            float e0 = __expf(v0 - Mnew);
            float e1 = __expf(v1 - Mnew);
            p_s[r*PADP + lane] = e0;
            p_s[r*PADP + 32 + lane] = e1;
            float sum = e0 + e1;
#pragma unroll
            for (int off=16; off; off>>=1) sum += __shfl_xor_sync(0xffffffffu, sum, off);
            if (lane==0){
                float alpha = __expf(Mold - Mnew);
                Arow[r] = alpha;
                Mrow[r] = Mnew;
                Lrow[r] = Lrow[r]*alpha + sum;
            }
        }
        __syncthreads();

        // rescale register accumulator + PV (vectorized dots)
        {
            float al[4];
#pragma unroll
            for (int i=0;i<4;i++) al[i] = Arow[ty*4+i];
#pragma unroll
            for (int i=0;i<4;i++)
#pragma unroll
                for (int j=0;j<4;j++) out[i][j] *= al[i];
        }
#pragma unroll 4
        for (int n4 = 0; n4 < 64; n4 += 4){
            float4 pr[4], vr[4];
#pragma unroll
            for (int i=0;i<4;i++)
                pr[i] = *(const float4*)&p_s[(ty*4+i)*PADP + n4];
#pragma unroll
            for (int j=0;j<4;j++){
                int c = tx*4 + j;
                vr[j] = *(const float4*)&v_s[c*PADP + (n4 ^ vxor(c))];
            }
#pragma unroll
            for (int i=0;i<4;i++)
#pragma unroll
                for (int j=0;j<4;j++)
                    out[i][j] += pr[i].x*vr[j].x + pr[i].y*vr[j].y
                               + pr[i].z*vr[j].z + pr[i].w*vr[j].w;
        }
        __syncthreads();   // before k_s/v_s/p_s overwrite next iter
    }

    // finalize: stage [c][m] in p_s then coalesced store
    {
        float li[4];
#pragma unroll
        for (int i=0;i<4;i++) li[i] = 1.f / Lrow[ty*4+i];
#pragma unroll
        for (int i=0;i<4;i++)
#pragma unroll
            for (int j=0;j<4;j++)
                p_s[(tx*4+j)*PADP + ty*4+i] = out[i][j]*li[i];
    }
    __syncthreads();
    for (int i = tid; i < 64*64; i += 256){
        int c = i >> 6, m = i & 63;
        g_o[((size_t)(b*Cch + h*HC + c))*HW + m0 + m] = p_s[c*PADP + m];
    }
}

// ---------------------------------------------------------------------------
extern "C" void kernel_launch(void* const* d_in, const int* in_sizes, int n_in,
                              void* d_out, int out_size)
{
    const float* x   = (const float*)d_in[0];
    const float* wq  = (const float*)d_in[1];
    const float* bq  = (const float*)d_in[2];
    const float* wk  = (const float*)d_in[3];
    const float* bk  = (const float*)d_in[4];
    const float* wv  = (const float*)d_in[5];
    const float* bv  = (const float*)d_in[6];
    const float* wo  = (const float*)d_in[7];
    const float* bo  = (const float*)d_in[8];
    const float* dww = (const float*)d_in[9];
    const float* dwb = (const float*)d_in[10];
    const float* lnw = (const float*)d_in[11];
    const float* lnb = (const float*)d_in[12];
    const float* pww = (const float*)d_in[13];
    const float* rpe = (const float*)d_in[14];
    float* out = (float*)d_out;

    void *pq, *pxs, *pk, *pv, *po;
    cudaGetSymbolAddress(&pq,  g_q);
    cudaGetSymbolAddress(&pxs, g_xs);
    cudaGetSymbolAddress(&pk,  g_k);
    cudaGetSymbolAddress(&pv,  g_v);
    cudaGetSymbolAddress(&po,  g_o);
    cudaFuncSetAttribute(attn_kernel, cudaFuncAttributeMaxDynamicSharedMemorySize,
                         21760 * (int)sizeof(float));

    const int write_pr = (out_size >= Bn*Cch*HW + 2*Bn*Gn*Npts*2) ? 1 : 0;
    float* posref = out + Bn*Cch*HW;

    const dim3 gg(HW/128, Cch/128, Bn);
    gemm_pw<<<gg, 256>>>(wq, x, bq, (float*)pq);
    offset_kernel<<<dim3(Npts, Bn*Gn), 128>>>(dww, dwb, lnw, lnb, pww, posref, write_pr);
    sample_kernel<<<dim3(8, Bn*Gn), 256>>>(x);
    gemm_kv<<<dim3(HW/128, 8, Bn), 256>>>(wk, bk, (float*)pk,
                                          wv, bv, (float*)pv, (const float*)pxs);
    attn_kernel<<<dim3(HW/64, Bn*HEADS), 256, 21760*sizeof(float)>>>(rpe);
    gemm_pw<<<gg, 256>>>(wo, (const float*)po, bo, out);
}

// round 7
// speedup vs baseline: 1.3531x; 1.1651x over previous
#include <cuda_runtime.h>
#include <cuda_bf16.h>
#include <cstdint>
#include <math.h>

#define Bn 4
#define Cch 512
#define HW 1024
#define HEADS 8
#define HC 64
#define Gn 4
#define GC 128
#define Npts 1024
#define RS 63
#define PADQ 68
#define PADP 68

__device__ float g_q [Bn*Cch*HW];
__device__ float g_xs[Bn*Cch*Npts];
__device__ float g_k [Bn*Cch*Npts];
__device__ float g_v [Bn*Cch*Npts];
__device__ float g_o [Bn*Cch*HW];
__device__ float g_pos[Bn*Gn*Npts*2];
__device__ __nv_bfloat16 g_wh [4*Cch*Cch];
__device__ __nv_bfloat16 g_wl [4*Cch*Cch];
__device__ __nv_bfloat16 g_xth[Bn*HW*Cch];
__device__ __nv_bfloat16 g_xtl[Bn*HW*Cch];

__device__ __forceinline__ int vxor(int c){ return ((c>>3)&7)<<2; }

#define MMA_BF16(d, a0,a1,a2,a3, b0,b1) \
    asm volatile("mma.sync.aligned.m16n8k16.row.col.f32.bf16.bf16.f32 " \
        "{%0,%1,%2,%3},{%4,%5,%6,%7},{%8,%9},{%0,%1,%2,%3};" \
        : "+f"((d)[0]), "+f"((d)[1]), "+f"((d)[2]), "+f"((d)[3]) \
        : "r"(a0), "r"(a1), "r"(a2), "r"(a3), "r"(b0), "r"(b1))

__global__ __launch_bounds__(256) void convert_w(
    const float* __restrict__ w0, const float* __restrict__ w1,
    const float* __restrict__ w2, const float* __restrict__ w3)
{
    const int sel = blockIdx.y;
    const float* w = sel==0 ? w0 : sel==1 ? w1 : sel==2 ? w2 : w3;
    const int idx = blockIdx.x*256 + threadIdx.x;
    float v = w[idx];
    __nv_bfloat16 hi = __float2bfloat16(v);
    g_wh[sel*Cch*Cch + idx] = hi;
    g_wl[sel*Cch*Cch + idx] = __float2bfloat16(v - __bfloat162float(hi));
}

__global__ __launch_bounds__(256) void trans_conv(const float* __restrict__ X)
{
    __shared__ float tile[32][33];
    const int b = blockIdx.z;
    const int p0 = blockIdx.x*32, c0 = blockIdx.y*32;
    const int tx = threadIdx.x & 31, ty = threadIdx.x >> 5;
#pragma unroll
    for (int i = 0; i < 4; i++){
        int c = c0 + ty + i*8;
        tile[ty + i*8][tx] = X[((size_t)b*Cch + c)*HW + p0 + tx];
    }
    __syncthreads();
#pragma unroll
    for (int i = 0; i < 4; i++){
        int p = p0 + ty + i*8;
        int c = c0 + tx;
        float v = tile[tx][ty + i*8];
        __nv_bfloat16 hi = __float2bfloat16(v);
        g_xth[((size_t)b*HW + p)*Cch + c] = hi;
        g_xtl[((size_t)b*HW + p)*Cch + c] = __float2bfloat16(v - __bfloat162float(hi));
    }
}

__global__ __launch_bounds__(256) void gemm_mma(
    const __nv_bfloat16* __restrict__ Wh, const __nv_bfloat16* __restrict__ Wl,
    const float* __restrict__ bias, float* __restrict__ Y)
{
    __shared__ __nv_bfloat16 Ah_s[128][40];
    __shared__ __nv_bfloat16 Al_s[128][40];
    __shared__ __nv_bfloat16 Bh_s[128][40];
    __shared__ __nv_bfloat16 Bl_s[128][40];

    const int b  = blockIdx.z;
    const int o0 = blockIdx.y * 128;
    const int p0 = blockIdx.x * 128;
    const int tid = threadIdx.x, lane = tid & 31, wid = tid >> 5;
    const int wm = wid >> 1, wn = wid & 1;
    const int g = lane >> 2, q4 = lane & 3;

    float acc[2][8][4];
#pragma unroll
    for (int mf=0; mf<2; mf++)
#pragma unroll
        for (int nf=0; nf<8; nf++)
#pragma unroll
            for (int r=0; r<4; r++) acc[mf][nf][r] = 0.f;

    const __nv_bfloat16* wh  = Wh + (size_t)o0*Cch;
    const __nv_bfloat16* wl  = Wl + (size_t)o0*Cch;
    const __nv_bfloat16* xth = g_xth + ((size_t)b*HW + p0)*Cch;
    const __nv_bfloat16* xtl = g_xtl + ((size_t)b*HW + p0)*Cch;

    for (int kc = 0; kc < 16; kc++){
        const int k0 = kc * 32;
        __syncthreads();
#pragma unroll
        for (int i = 0; i < 8; i++){
            const int job = tid + i*256;
            const int chunk = (job & 3) * 8;
            const int row = (job >> 2) & 127;
            const int arr = job >> 9;
            const __nv_bfloat16* src;
            __nv_bfloat16* dst;
            if      (arr == 0){ src = wh  + (size_t)row*Cch + k0; dst = &Ah_s[row][0]; }
            else if (arr == 1){ src = wl  + (size_t)row*Cch + k0; dst = &Al_s[row][0]; }
            else if (arr == 2){ src = xth + (size_t)row*Cch + k0; dst = &Bh_s[row][0]; }
            else              { src = xtl + (size_t)row*Cch + k0; dst = &Bl_s[row][0]; }
            *(uint4*)(dst + chunk) = *(const uint4*)(src + chunk);
        }
        __syncthreads();

#pragma unroll
        for (int k16 = 0; k16 < 2; k16++){
            const int kb = k16*16 + q4*2;
            uint32_t ah[2][4], al[2][4];
#pragma unroll
            for (int mf=0; mf<2; mf++){
                const int r = wm*32 + mf*16 + g;
                ah[mf][0] = *(const uint32_t*)&Ah_s[r  ][kb];
                ah[mf][1] = *(const uint32_t*)&Ah_s[r+8][kb];
                ah[mf][2] = *(const uint32_t*)&Ah_s[r  ][kb+8];
                ah[mf][3] = *(const uint32_t*)&Ah_s[r+8][kb+8];
                al[mf][0] = *(const uint32_t*)&Al_s[r  ][kb];
                al[mf][1] = *(const uint32_t*)&Al_s[r+8][kb];
                al[mf][2] = *(const uint32_t*)&Al_s[r  ][kb+8];
                al[mf][3] = *(const uint32_t*)&Al_s[r+8][kb+8];
            }
#pragma unroll
            for (int nf=0; nf<8; nf++){
                const int n = wn*64 + nf*8 + g;
                const uint32_t bh0 = *(const uint32_t*)&Bh_s[n][kb];
                const uint32_t bh1 = *(const uint32_t*)&Bh_s[n][kb+8];
                const uint32_t bl0 = *(const uint32_t*)&Bl_s[n][kb];
                const uint32_t bl1 = *(const uint32_t*)&Bl_s[n][kb+8];
#pragma unroll
                for (int mf=0; mf<2; mf++){
                    MMA_BF16(acc[mf][nf], ah[mf][0],ah[mf][1],ah[mf][2],ah[mf][3], bh0,bh1);
                    MMA_BF16(acc[mf][nf], ah[mf][0],ah[mf][1],ah[mf][2],ah[mf][3], bl0,bl1);
                    MMA_BF16(acc[mf][nf], al[mf][0],al[mf][1],al[mf][2],al[mf][3], bh0,bh1);
                }
            }
        }
    }

#pragma unroll
    for (int mf=0; mf<2; mf++){
        const int o = o0 + wm*32 + mf*16 + g;
        const float bv0 = bias[o], bv8 = bias[o+8];
#pragma unroll
        for (int nf=0; nf<8; nf++){
            const int p = p0 + wn*64 + nf*8 + q4*2;
            float2 lo2, hi2;
            lo2.x = acc[mf][nf][0] + bv0; lo2.y = acc[mf][nf][1] + bv0;
            hi2.x = acc[mf][nf][2] + bv8; hi2.y = acc[mf][nf][3] + bv8;
            *(float2*)(Y + ((size_t)b*Cch + o  )*HW + p) = lo2;
            *(float2*)(Y + ((size_t)b*Cch + o+8)*HW + p) = hi2;
        }
    }
}

__global__ __launch_bounds__(128) void offset_kernel(
    const float* __restrict__ dw_w, const float* __restrict__ dw_b,
    const float* __restrict__ ln_w, const float* __restrict__ ln_b,
    const float* __restrict__ pw_w, float* __restrict__ posref, int write_pr)
{
    const int p  = blockIdx.x;
    const int bg = blockIdx.y;
    const int ch = threadIdx.x;
    const int y = p >> 5, x = p & 31;
    const int b = bg >> 2, g = bg & 3;

    const float* qp = g_q + ((size_t)(b*Cch + g*GC + ch)) * HW;
    float v = dw_b[ch];
#pragma unroll
    for (int ky = 0; ky < 3; ky++){
        int yy = y + ky - 1;
        if (yy < 0 || yy > 31) continue;
#pragma unroll
        for (int kx = 0; kx < 3; kx++){
            int xx = x + kx - 1;
            if (xx < 0 || xx > 31) continue;
            v += qp[yy*32+xx] * dw_w[ch*9 + ky*3 + kx];
        }
    }
    __shared__ float red[4];
    __shared__ float red2[2][4];
    float s = v;
#pragma unroll
    for (int off=16; off; off>>=1) s += __shfl_xor_sync(0xffffffffu, s, off);
    if ((ch&31)==0) red[ch>>5] = s;
    __syncthreads();
    float mean = (red[0]+red[1]+red[2]+red[3]) * (1.f/128.f);
    __syncthreads();
    float d = v - mean;
    s = d*d;
#pragma unroll
    for (int off=16; off; off>>=1) s += __shfl_xor_sync(0xffffffffu, s, off);
    if ((ch&31)==0) red[ch>>5] = s;
    __syncthreads();
    float var = (red[0]+red[1]+red[2]+red[3]) * (1.f/128.f);
    float o = d * rsqrtf(var + 1e-5f) * ln_w[ch] + ln_b[ch];
    o = 0.5f * o * (1.f + erff(o * 0.70710678118654752440f));
    float s0 = o * pw_w[ch];
    float s1 = o * pw_w[128+ch];
#pragma unroll
    for (int off=16; off; off>>=1){
        s0 += __shfl_xor_sync(0xffffffffu, s0, off);
        s1 += __shfl_xor_sync(0xffffffffu, s1, off);
    }
    if ((ch&31)==0){ red2[0][ch>>5]=s0; red2[1][ch>>5]=s1; }
    __syncthreads();
    if (ch == 0){
        float offy = red2[0][0]+red2[0][1]+red2[0][2]+red2[0][3];
        float offx = red2[1][0]+red2[1][1]+red2[1][2]+red2[1][3];
        float ry = ((y+0.5f)/31.f)*2.f - 1.f;
        float rx = ((x+0.5f)/31.f)*2.f - 1.f;
        float py = fminf(fmaxf(offy+ry, -1.f), 1.f);
        float px = fminf(fmaxf(offx+rx, -1.f), 1.f);
        int idx = (bg*Npts + p)*2;
        g_pos[idx+0] = py;
        g_pos[idx+1] = px;
        if (write_pr){
            posref[idx+0] = py;
            posref[idx+1] = px;
            posref[Bn*Gn*Npts*2 + idx + 0] = ry;
            posref[Bn*Gn*Npts*2 + idx + 1] = rx;
        }
    }
}

__global__ __launch_bounds__(256) void sample_kernel(const float* __restrict__ x)
{
    const int cc = blockIdx.x;
    const int bg = blockIdx.y;
    const int b = bg >> 2, g = bg & 3;
    for (int n = threadIdx.x; n < Npts; n += 256){
        float py = g_pos[(bg*Npts+n)*2+0];
        float px = g_pos[(bg*Npts+n)*2+1];
        float gx = (px+1.f)*0.5f*31.f;
        float gy = (py+1.f)*0.5f*31.f;
        float x0f = floorf(gx), y0f = floorf(gy);
        float wx = gx-x0f, wy = gy-y0f;
        int x0 = max(min((int)x0f, 31), 0);
        int y0 = max(min((int)y0f, 31), 0);
        int x1 = min(x0+1, 31);
        int y1 = min(y0+1, 31);
        float w00 = (1.f-wx)*(1.f-wy), w10 = wx*(1.f-wy);
        float w01 = (1.f-wx)*wy,       w11 = wx*wy;
        for (int cj = 0; cj < 16; cj++){
            int cfull = g*GC + cc*16 + cj;
            const float* pl = x + ((size_t)(b*Cch + cfull))*HW;
            float val = pl[y0*32+x0]*w00 + pl[y0*32+x1]*w10
                      + pl[y1*32+x0]*w01 + pl[y1*32+x1]*w11;
            g_xs[((size_t)(b*Cch + cfull))*Npts + n] = val;
        }
    }
}

__global__ __launch_bounds__(256) void attn_kernel(const float* __restrict__ rpe)
{
    extern __shared__ float sm[];
    float* rpe_s = sm;
    float* q_s   = rpe_s + 4032;
    float* k_s   = q_s + 4352;
    float* v_s   = k_s + 4352;
    float* p_s   = v_s + 4352;
    float* py_s  = p_s + 4352;
    float* px_s  = py_s + 64;
    float* Mrow  = px_s + 64;
    float* Lrow  = Mrow + 64;
    float* Arow  = Lrow + 64;

    const int tid = threadIdx.x;
    const int bh = blockIdx.y;
    const int m0 = blockIdx.x * 64;
    const int b = bh >> 3, h = bh & 7, g = h >> 1;
    const int lane = tid & 31, warp = tid >> 5;
    const int tx = tid & 15;
    const int ty = tid >> 4;
    const int bg = b*Gn + g;

    const float* rh = rpe + (size_t)h*RS*RS;
    for (int i = tid; i < RS*RS; i += 256) rpe_s[(i/RS)*64 + (i%RS)] = rh[i];

    const float* qb = g_q + ((size_t)(b*Cch + h*HC))*HW + m0;
    for (int i = tid; i < 64*64; i += 256){
        int c = i >> 6, m = i & 63;
        q_s[c*PADQ + m] = qb[(size_t)c*HW + m];
    }
    if (tid < 64){ Mrow[tid] = -1e30f; Lrow[tid] = 0.f; }

    float out[4][4];
#pragma unroll
    for (int i=0;i<4;i++)
#pragma unroll
        for (int j=0;j<4;j++) out[i][j]=0.f;

    float qy[4], qx[4];
#pragma unroll
    for (int i=0;i<4;i++){
        int mg = m0 + ty*4 + i;
        qy[i] = (float)(mg>>5) * (2.f/31.f) - 1.f;
        qx[i] = (float)(mg&31) * (2.f/31.f) - 1.f;
    }

    const float* kb = g_k + ((size_t)(b*Cch + h*HC))*Npts;
    const float* vb = g_v + ((size_t)(b*Cch + h*HC))*Npts;

    __syncthreads();

    for (int t = 0; t < Npts; t += 64){
        for (int i = tid; i < 64*64; i += 256){
            int c = i >> 6, n = i & 63;
            k_s[c*PADQ + n] = kb[(size_t)c*Npts + t + n];
            v_s[c*PADP + (n ^ vxor(c))] = vb[(size_t)c*Npts + t + n];
        }
        if (tid < 64){
            py_s[tid] = g_pos[((size_t)bg*Npts + t + tid)*2 + 0];
            px_s[tid] = g_pos[((size_t)bg*Npts + t + tid)*2 + 1];
        }
        __syncthreads();

        float s4[4][4];
#pragma unroll
        for (int i=0;i<4;i++)
#pragma unroll
            for (int j=0;j<4;j++) s4[i][j]=0.f;
#pragma unroll 8
        for (int c = 0; c < HC; c++){
            float a[4], bb[4];
            *(float4*)a  = *(const float4*)&q_s[c*PADQ + ty*4];
            *(float4*)bb = *(const float4*)&k_s[c*PADQ + tx*4];
#pragma unroll
            for (int i=0;i<4;i++)
#pragma unroll
                for (int j=0;j<4;j++) s4[i][j] += a[i]*bb[j];
        }
#pragma unroll
        for (int j=0;j<4;j++){
            int n = tx*4 + j;
            float py = py_s[n], px = px_s[n];
#pragma unroll
            for (int i=0;i<4;i++){
                float gx = ((qx[i]-px)*0.5f + 1.f)*31.f;
                float gy = ((qy[i]-py)*0.5f + 1.f)*31.f;
                float x0f = floorf(gx), y0f = floorf(gy);
                float wx = gx-x0f, wy = gy-y0f;
                int x0 = max(min((int)x0f, 62), 0);
                int y0 = max(min((int)y0f, 62), 0);
                int x1 = min(x0+1, 62);
                int y1 = min(y0+1, 62);
                float r00 = rpe_s[y0*64+x0], r01 = rpe_s[y0*64+x1];
                float r10 = rpe_s[y1*64+x0], r11 = rpe_s[y1*64+x1];
                float top = r00 + (r01-r00)*wx;
                float bot = r10 + (r11-r10)*wx;
                float bias = top + (bot-top)*wy;
                s4[i][j] = s4[i][j]*0.125f + bias;
            }
        }
#pragma unroll
        for (int i=0;i<4;i++)
            *(float4*)&p_s[(ty*4+i)*PADP + tx*4] = *(float4*)&s4[i][0];
        __syncthreads();

#pragma unroll
        for (int rr = 0; rr < 8; rr++){
            int r = warp*8 + rr;
            float v0 = p_s[r*PADP + lane];
            float v1 = p_s[r*PADP + 32 + lane];
            float mx = fmaxf(v0, v1);
#pragma unroll
            for (int off=16; off; off>>=1) mx = fmaxf(mx, __shfl_xor_sync(0xffffffffu, mx, off));
            float Mold = Mrow[r];
            float Mnew = fmaxf(Mold, mx);
            float e0 = __expf(v0 - Mnew);
            float e1 = __expf(v1 - Mnew);
            p_s[r*PADP + lane] = e0;
            p_s[r*PADP + 32 + lane] = e1;
            float sum = e0 + e1;
#pragma unroll
            for (int off=16; off; off>>=1) sum += __shfl_xor_sync(0xffffffffu, sum, off);
            if (lane==0){
                float alpha = __expf(Mold - Mnew);
                Arow[r] = alpha;
                Mrow[r] = Mnew;
                Lrow[r] = Lrow[r]*alpha + sum;
            }
        }
        __syncthreads();

        {
            float al[4];
#pragma unroll
            for (int i=0;i<4;i++) al[i] = Arow[ty*4+i];
#pragma unroll
            for (int i=0;i<4;i++)
#pragma unroll
                for (int j=0;j<4;j++) out[i][j] *= al[i];
        }
#pragma unroll 4
        for (int n4 = 0; n4 < 64; n4 += 4){
            float4 pr[4], vr[4];
#pragma unroll
            for (int i=0;i<4;i++)
                pr[i] = *(const float4*)&p_s[(ty*4+i)*PADP + n4];
#pragma unroll
            for (int j=0;j<4;j++){
                int c = tx*4 + j;
                vr[j] = *(const float4*)&v_s[c*PADP + (n4 ^ vxor(c))];
            }
#pragma unroll
            for (int i=0;i<4;i++)
#pragma unroll
                for (int j=0;j<4;j++)
                    out[i][j] += pr[i].x*vr[j].x + pr[i].y*vr[j].y
                               + pr[i].z*vr[j].z + pr[i].w*vr[j].w;
        }
        __syncthreads();
    }

    {
        float li[4];
#pragma unroll
        for (int i=0;i<4;i++) li[i] = 1.f / Lrow[ty*4+i];
#pragma unroll
        for (int i=0;i<4;i++)
#pragma unroll
            for (int j=0;j<4;j++)
                p_s[(tx*4+j)*PADP + ty*4+i] = out[i][j]*li[i];
    }
    __syncthreads();
    for (int i = tid; i < 64*64; i += 256){
        int c = i >> 6, m = i & 63;
        g_o[((size_t)(b*Cch + h*HC + c))*HW + m0 + m] = p_s[c*PADP + m];
    }
}

extern "C" void kernel_launch(void* const* d_in, const int* in_sizes, int n_in,
                              void* d_out, int out_size)
{
    const float* x   = (const float*)d_in[0];
    const float* wq  = (const float*)d_in[1];
    const float* bq  = (const float*)d_in[2];
    const float* wk  = (const float*)d_in[3];
    const float* bk  = (const float*)d_in[4];
    const float* wv  = (const float*)d_in[5];
    const float* bv  = (const float*)d_in[6];
    const float* wo  = (const float*)d_in[7];
    const float* bo  = (const float*)d_in[8];
    const float* dww = (const float*)d_in[9];
    const float* dwb = (const float*)d_in[10];
    const float* lnw = (const float*)d_in[11];
    const float* lnb = (const float*)d_in[12];
    const float* pww = (const float*)d_in[13];
    const float* rpe = (const float*)d_in[14];
    float* out = (float*)d_out;

    void *pq, *pxs, *pk, *pv, *po, *pwh, *pwl;
    cudaGetSymbolAddress(&pq,  g_q);
    cudaGetSymbolAddress(&pxs, g_xs);
    cudaGetSymbolAddress(&pk,  g_k);
    cudaGetSymbolAddress(&pv,  g_v);
    cudaGetSymbolAddress(&po,  g_o);
    cudaGetSymbolAddress(&pwh, g_wh);
    cudaGetSymbolAddress(&pwl, g_wl);
    cudaFuncSetAttribute(attn_kernel, cudaFuncAttributeMaxDynamicSharedMemorySize,
                         21760 * (int)sizeof(float));

    const __nv_bfloat16* wh = (const __nv_bfloat16*)pwh;
    const __nv_bfloat16* wl = (const __nv_bfloat16*)pwl;

    const int write_pr = (out_size >= Bn*Cch*HW + 2*Bn*Gn*Npts*2) ? 1 : 0;
    float* posref = out + Bn*Cch*HW;

    const dim3 gmm(HW/128, Cch/128, Bn);
    const dim3 gtr(HW/32, Cch/32, Bn);

    convert_w<<<dim3(Cch*Cch/256, 4), 256>>>(wq, wk, wv, wo);
    trans_conv<<<gtr, 256>>>(x);
    gemm_mma<<<gmm, 256>>>(wh + 0*Cch*Cch, wl + 0*Cch*Cch, bq, (float*)pq);
    offset_kernel<<<dim3(Npts, Bn*Gn), 128>>>(dww, dwb, lnw, lnb, pww, posref, write_pr);
    sample_kernel<<<dim3(8, Bn*Gn), 256>>>(x);
    trans_conv<<<gtr, 256>>>((const float*)pxs);
    gemm_mma<<<gmm, 256>>>(wh + 1*Cch*Cch, wl + 1*Cch*Cch, bk, (float*)pk);
    gemm_mma<<<gmm, 256>>>(wh + 2*Cch*Cch, wl + 2*Cch*Cch, bv, (float*)pv);
    attn_kernel<<<dim3(HW/64, Bn*HEADS), 256, 21760*sizeof(float)>>>(rpe);
    trans_conv<<<gtr, 256>>>((const float*)po);
    gemm_mma<<<gmm, 256>>>(wh + 3*Cch*Cch, wl + 3*Cch*Cch, bo, out);
}

// round 8
// speedup vs baseline: 1.8465x; 1.3647x over previous
#include <cuda_runtime.h>
#include <cuda_bf16.h>
#include <cstdint>
#include <math.h>

#define Bn 4
#define Cch 512
#define HW 1024
#define HEADS 8
#define HC 64
#define Gn 4
#define GC 128
#define Npts 1024
#define RS 63

__device__ float g_q [Bn*Cch*HW];
__device__ float g_xs[Bn*Cch*Npts];
__device__ float g_k [Bn*Cch*Npts];
__device__ float g_v [Bn*Cch*Npts];
__device__ float g_o [Bn*Cch*HW];
__device__ float g_pos[Bn*Gn*Npts*2];
__device__ __nv_bfloat16 g_wh [4*Cch*Cch];
__device__ __nv_bfloat16 g_wl [4*Cch*Cch];
__device__ __nv_bfloat16 g_xth[Bn*HW*Cch];
__device__ __nv_bfloat16 g_xtl[Bn*HW*Cch];

#define MMA_BF16(d, a0,a1,a2,a3, b0,b1) \
    asm volatile("mma.sync.aligned.m16n8k16.row.col.f32.bf16.bf16.f32 " \
        "{%0,%1,%2,%3},{%4,%5,%6,%7},{%8,%9},{%0,%1,%2,%3};" \
        : "+f"((d)[0]), "+f"((d)[1]), "+f"((d)[2]), "+f"((d)[3]) \
        : "r"(a0), "r"(a1), "r"(a2), "r"(a3), "r"(b0), "r"(b1))

__device__ __forceinline__ uint32_t packbf(float a, float b){
    __nv_bfloat162 t = __floats2bfloat162_rn(a, b);
    return *(uint32_t*)&t;
}

// ---------------------------------------------------------------------------
__global__ __launch_bounds__(256) void convert_w(
    const float* __restrict__ w0, const float* __restrict__ w1,
    const float* __restrict__ w2, const float* __restrict__ w3)
{
    const int sel = blockIdx.y;
    const float* w = sel==0 ? w0 : sel==1 ? w1 : sel==2 ? w2 : w3;
    const int idx = blockIdx.x*256 + threadIdx.x;
    float v = w[idx];
    __nv_bfloat16 hi = __float2bfloat16(v);
    g_wh[sel*Cch*Cch + idx] = hi;
    g_wl[sel*Cch*Cch + idx] = __float2bfloat16(v - __bfloat162float(hi));
}

__global__ __launch_bounds__(256) void trans_conv(const float* __restrict__ X)
{
    __shared__ float tile[32][33];
    const int b = blockIdx.z;
    const int p0 = blockIdx.x*32, c0 = blockIdx.y*32;
    const int tx = threadIdx.x & 31, ty = threadIdx.x >> 5;
#pragma unroll
    for (int i = 0; i < 4; i++){
        int c = c0 + ty + i*8;
        tile[ty + i*8][tx] = X[((size_t)b*Cch + c)*HW + p0 + tx];
    }
    __syncthreads();
#pragma unroll
    for (int i = 0; i < 4; i++){
        int p = p0 + ty + i*8;
        int c = c0 + tx;
        float v = tile[tx][ty + i*8];
        __nv_bfloat16 hi = __float2bfloat16(v);
        g_xth[((size_t)b*HW + p)*Cch + c] = hi;
        g_xtl[((size_t)b*HW + p)*Cch + c] = __float2bfloat16(v - __bfloat162float(hi));
    }
}

__global__ __launch_bounds__(256) void gemm_mma(
    const __nv_bfloat16* __restrict__ Wh, const __nv_bfloat16* __restrict__ Wl,
    const float* __restrict__ bias, float* __restrict__ Y)
{
    __shared__ __nv_bfloat16 Ah_s[128][40];
    __shared__ __nv_bfloat16 Al_s[128][40];
    __shared__ __nv_bfloat16 Bh_s[128][40];
    __shared__ __nv_bfloat16 Bl_s[128][40];

    const int b  = blockIdx.z;
    const int o0 = blockIdx.y * 128;
    const int p0 = blockIdx.x * 128;
    const int tid = threadIdx.x, lane = tid & 31, wid = tid >> 5;
    const int wm = wid >> 1, wn = wid & 1;
    const int g = lane >> 2, q4 = lane & 3;

    float acc[2][8][4];
#pragma unroll
    for (int mf=0; mf<2; mf++)
#pragma unroll
        for (int nf=0; nf<8; nf++)
#pragma unroll
            for (int r=0; r<4; r++) acc[mf][nf][r] = 0.f;

    const __nv_bfloat16* wh  = Wh + (size_t)o0*Cch;
    const __nv_bfloat16* wl  = Wl + (size_t)o0*Cch;
    const __nv_bfloat16* xth = g_xth + ((size_t)b*HW + p0)*Cch;
    const __nv_bfloat16* xtl = g_xtl + ((size_t)b*HW + p0)*Cch;

    for (int kc = 0; kc < 16; kc++){
        const int k0 = kc * 32;
        __syncthreads();
#pragma unroll
        for (int i = 0; i < 8; i++){
            const int job = tid + i*256;
            const int chunk = (job & 3) * 8;
            const int row = (job >> 2) & 127;
            const int arr = job >> 9;
            const __nv_bfloat16* src;
            __nv_bfloat16* dst;
            if      (arr == 0){ src = wh  + (size_t)row*Cch + k0; dst = &Ah_s[row][0]; }
            else if (arr == 1){ src = wl  + (size_t)row*Cch + k0; dst = &Al_s[row][0]; }
            else if (arr == 2){ src = xth + (size_t)row*Cch + k0; dst = &Bh_s[row][0]; }
            else              { src = xtl + (size_t)row*Cch + k0; dst = &Bl_s[row][0]; }
            *(uint4*)(dst + chunk) = *(const uint4*)(src + chunk);
        }
        __syncthreads();

#pragma unroll
        for (int k16 = 0; k16 < 2; k16++){
            const int kb = k16*16 + q4*2;
            uint32_t ah[2][4], al[2][4];
#pragma unroll
            for (int mf=0; mf<2; mf++){
                const int r = wm*32 + mf*16 + g;
                ah[mf][0] = *(const uint32_t*)&Ah_s[r  ][kb];
                ah[mf][1] = *(const uint32_t*)&Ah_s[r+8][kb];
                ah[mf][2] = *(const uint32_t*)&Ah_s[r  ][kb+8];
                ah[mf][3] = *(const uint32_t*)&Ah_s[r+8][kb+8];
                al[mf][0] = *(const uint32_t*)&Al_s[r  ][kb];
                al[mf][1] = *(const uint32_t*)&Al_s[r+8][kb];
                al[mf][2] = *(const uint32_t*)&Al_s[r  ][kb+8];
                al[mf][3] = *(const uint32_t*)&Al_s[r+8][kb+8];
            }
#pragma unroll
            for (int nf=0; nf<8; nf++){
                const int n = wn*64 + nf*8 + g;
                const uint32_t bh0 = *(const uint32_t*)&Bh_s[n][kb];
                const uint32_t bh1 = *(const uint32_t*)&Bh_s[n][kb+8];
                const uint32_t bl0 = *(const uint32_t*)&Bl_s[n][kb];
                const uint32_t bl1 = *(const uint32_t*)&Bl_s[n][kb+8];
#pragma unroll
                for (int mf=0; mf<2; mf++){
                    MMA_BF16(acc[mf][nf], ah[mf][0],ah[mf][1],ah[mf][2],ah[mf][3], bh0,bh1);
                    MMA_BF16(acc[mf][nf], ah[mf][0],ah[mf][1],ah[mf][2],ah[mf][3], bl0,bl1);
                    MMA_BF16(acc[mf][nf], al[mf][0],al[mf][1],al[mf][2],al[mf][3], bh0,bh1);
                }
            }
        }
    }

#pragma unroll
    for (int mf=0; mf<2; mf++){
        const int o = o0 + wm*32 + mf*16 + g;
        const float bv0 = bias[o], bv8 = bias[o+8];
#pragma unroll
        for (int nf=0; nf<8; nf++){
            const int p = p0 + wn*64 + nf*8 + q4*2;
            float2 lo2, hi2;
            lo2.x = acc[mf][nf][0] + bv0; lo2.y = acc[mf][nf][1] + bv0;
            hi2.x = acc[mf][nf][2] + bv8; hi2.y = acc[mf][nf][3] + bv8;
            *(float2*)(Y + ((size_t)b*Cch + o  )*HW + p) = lo2;
            *(float2*)(Y + ((size_t)b*Cch + o+8)*HW + p) = hi2;
        }
    }
}

// ---------------------------------------------------------------------------
// Offset network v2: block=(row y, bg), 256 threads = 2 px x 128 ch.
// Dyn smem: 3*128*32 + 8 + 8 + 16 floats = 12320 f = 49280 B.
// ---------------------------------------------------------------------------
__global__ __launch_bounds__(256) void offset_kernel(
    const float* __restrict__ dw_w, const float* __restrict__ dw_b,
    const float* __restrict__ ln_w, const float* __restrict__ ln_b,
    const float* __restrict__ pw_w, float* __restrict__ posref, int write_pr)
{
    extern __shared__ float osm[];
    float* qs   = osm;              // [3][128][32]
    float* redA = qs + 12288;       // [2][4]
    float* redB = redA + 8;         // [2][4]
    float* redC = redB + 8;         // [2][2][4]

    const int y  = blockIdx.x;       // 0..31
    const int bg = blockIdx.y;       // 0..15
    const int tid = threadIdx.x;
    const int ch = tid & 127;
    const int half = tid >> 7;
    const int lane = tid & 31;
    const int w4 = (tid >> 5) & 3;
    const int b = bg >> 2, g = bg & 3;

    // stage 3 rows of all 128 channels
    for (int i = tid; i < 3*128*32; i += 256){
        int r = i >> 12, rem = i & 4095;
        int cl = rem >> 5, xx = rem & 31;
        int yy = y - 1 + r;
        if (yy >= 0 && yy < 32)
            qs[i] = g_q[((size_t)(b*Cch + g*GC + cl))*HW + yy*32 + xx];
    }
    bool rv[3];
    rv[0] = (y-1 >= 0); rv[1] = true; rv[2] = (y+1 < 32);

    float wreg[9];
#pragma unroll
    for (int k = 0; k < 9; k++) wreg[k] = dw_w[ch*9 + k];
    const float dwbr = dw_b[ch];
    const float lnwr = ln_w[ch], lnbr = ln_b[ch];
    const float pw0 = pw_w[ch], pw1 = pw_w[128+ch];
    __syncthreads();

    for (int it = 0; it < 16; it++){
        const int x = it*2 + half;
        float v = dwbr;
#pragma unroll
        for (int ky = 0; ky < 3; ky++){
            if (!rv[ky]) continue;
            const float* row = qs + (ky*128 + ch)*32;
#pragma unroll
            for (int kx = 0; kx < 3; kx++){
                int xx = x + kx - 1;
                if (xx < 0 || xx > 31) continue;
                v += row[xx] * wreg[ky*3 + kx];
            }
        }
        float s = v;
#pragma unroll
        for (int off=16; off; off>>=1) s += __shfl_xor_sync(0xffffffffu, s, off);
        if (lane==0) redA[half*4 + w4] = s;
        __syncthreads();
        float mean = (redA[half*4]+redA[half*4+1]+redA[half*4+2]+redA[half*4+3]) * (1.f/128.f);
        float d = v - mean;
        s = d*d;
#pragma unroll
        for (int off=16; off; off>>=1) s += __shfl_xor_sync(0xffffffffu, s, off);
        if (lane==0) redB[half*4 + w4] = s;
        __syncthreads();
        float var = (redB[half*4]+redB[half*4+1]+redB[half*4+2]+redB[half*4+3]) * (1.f/128.f);
        float o = d * rsqrtf(var + 1e-5f) * lnwr + lnbr;
        o = 0.5f * o * (1.f + erff(o * 0.70710678118654752440f));
        float s0 = o * pw0, s1 = o * pw1;
#pragma unroll
        for (int off=16; off; off>>=1){
            s0 += __shfl_xor_sync(0xffffffffu, s0, off);
            s1 += __shfl_xor_sync(0xffffffffu, s1, off);
        }
        if (lane==0){ redC[half*4 + w4] = s0; redC[8 + half*4 + w4] = s1; }
        __syncthreads();
        if (ch == 0){
            float offy = redC[half*4]+redC[half*4+1]+redC[half*4+2]+redC[half*4+3];
            float offx = redC[8+half*4]+redC[8+half*4+1]+redC[8+half*4+2]+redC[8+half*4+3];
            float ry = ((y+0.5f)/31.f)*2.f - 1.f;
            float rx = ((x+0.5f)/31.f)*2.f - 1.f;
            float py = fminf(fmaxf(offy+ry, -1.f), 1.f);
            float px = fminf(fmaxf(offx+rx, -1.f), 1.f);
            int idx = (bg*Npts + y*32 + x)*2;
            g_pos[idx+0] = py;
            g_pos[idx+1] = px;
            if (write_pr){
                posref[idx+0] = py;
                posref[idx+1] = px;
                posref[Bn*Gn*Npts*2 + idx + 0] = ry;
                posref[Bn*Gn*Npts*2 + idx + 1] = rx;
            }
        }
        __syncthreads();
    }
}

// ---------------------------------------------------------------------------
__global__ __launch_bounds__(256) void sample_kernel(const float* __restrict__ x)
{
    const int cc = blockIdx.x;
    const int bg = blockIdx.y;
    const int b = bg >> 2, g = bg & 3;
    for (int n = threadIdx.x; n < Npts; n += 256){
        float py = g_pos[(bg*Npts+n)*2+0];
        float px = g_pos[(bg*Npts+n)*2+1];
        float gx = (px+1.f)*0.5f*31.f;
        float gy = (py+1.f)*0.5f*31.f;
        float x0f = floorf(gx), y0f = floorf(gy);
        float wx = gx-x0f, wy = gy-y0f;
        int x0 = max(min((int)x0f, 31), 0);
        int y0 = max(min((int)y0f, 31), 0);
        int x1 = min(x0+1, 31);
        int y1 = min(y0+1, 31);
        float w00 = (1.f-wx)*(1.f-wy), w10 = wx*(1.f-wy);
        float w01 = (1.f-wx)*wy,       w11 = wx*wy;
        for (int cj = 0; cj < 16; cj++){
            int cfull = g*GC + cc*16 + cj;
            const float* pl = x + ((size_t)(b*Cch + cfull))*HW;
            float val = pl[y0*32+x0]*w00 + pl[y0*32+x1]*w10
                      + pl[y1*32+x0]*w01 + pl[y1*32+x1]*w11;
            g_xs[((size_t)(b*Cch + cfull))*Npts + n] = val;
        }
    }
}

// ---------------------------------------------------------------------------
// Fused attention v4: tensor-core bf16x3 flash attention.
// Block=(m-tile 64, bh), 256 threads / 8 warps: wm=wid&3 (m16), wn=wid>>2 (n32).
// Dyn smem: floats 8960 (35840B) + bf16 6*64*72 (55296B) = 91136 B.
// ---------------------------------------------------------------------------
__global__ __launch_bounds__(256) void attn_kernel(const float* __restrict__ rpe)
{
    extern __shared__ char smraw[];
    float* rpe_s  = (float*)smraw;          // 4032
    float* pos_y  = rpe_s + 4032;           // 64
    float* pos_x  = pos_y + 64;             // 64
    float* Mrow   = pos_x + 64;             // 64
    float* Lrow   = Mrow + 64;              // 64
    float* Arow   = Lrow + 64;              // 64
    float* redmax = Arow + 64;              // 128 [row][wn]
    float* redsum = redmax + 128;           // 128
    float* outred = redsum + 128;           // 64*68 = 4352
    __nv_bfloat16* qh = (__nv_bfloat16*)(outred + 4352);
    __nv_bfloat16* ql = qh + 64*72;
    __nv_bfloat16* kh = ql + 64*72;
    __nv_bfloat16* kl = kh + 64*72;
    __nv_bfloat16* vh = kl + 64*72;
    __nv_bfloat16* vl = vh + 64*72;

    const int tid = threadIdx.x;
    const int bh = blockIdx.y;
    const int m0 = blockIdx.x * 64;
    const int b = bh >> 3, h = bh & 7, gg = h >> 1;
    const int lane = tid & 31, wid = tid >> 5;
    const int wm = wid & 3, wn = wid >> 2;
    const int g = lane >> 2, q4 = lane & 3;
    const int bg = b*Gn + gg;

    const float* rh = rpe + (size_t)h*RS*RS;
    for (int i = tid; i < RS*RS; i += 256) rpe_s[(i/RS)*64 + (i%RS)] = rh[i];

    const float* qb = g_q + ((size_t)(b*Cch + h*HC))*HW + m0;
    for (int i = tid; i < 64*64; i += 256){
        int c = i >> 6, m = i & 63;
        float qv = qb[(size_t)c*HW + m];
        __nv_bfloat16 hi = __float2bfloat16(qv);
        qh[m*72 + c] = hi;
        ql[m*72 + c] = __float2bfloat16(qv - __bfloat162float(hi));
    }
    if (tid < 64){ Mrow[tid] = -1e30f; Lrow[tid] = 0.f; }

    const int r0 = wm*16 + g, r1 = r0 + 8;
    const int mg0 = m0 + r0, mg1 = m0 + r1;
    const float qy0 = (float)(mg0>>5)*(2.f/31.f) - 1.f;
    const float qx0 = (float)(mg0&31)*(2.f/31.f) - 1.f;
    const float qy1 = (float)(mg1>>5)*(2.f/31.f) - 1.f;
    const float qx1 = (float)(mg1&31)*(2.f/31.f) - 1.f;

    const float* kb = g_k + ((size_t)(b*Cch + h*HC))*Npts;
    const float* vb = g_v + ((size_t)(b*Cch + h*HC))*Npts;

    float oacc[8][4];
#pragma unroll
    for (int fc=0; fc<8; fc++)
#pragma unroll
        for (int e=0; e<4; e++) oacc[fc][e] = 0.f;

    for (int t = 0; t < 16; t++){
        // load K/V tiles (hi/lo split) + pos
        for (int i = tid; i < 64*64; i += 256){
            int c = i >> 6, n = i & 63;
            float kv = kb[(size_t)c*Npts + t*64 + n];
            __nv_bfloat16 hk = __float2bfloat16(kv);
            kh[n*72 + c] = hk;
            kl[n*72 + c] = __float2bfloat16(kv - __bfloat162float(hk));
            float vv = vb[(size_t)c*Npts + t*64 + n];
            __nv_bfloat16 hv = __float2bfloat16(vv);
            vh[c*72 + n] = hv;
            vl[c*72 + n] = __float2bfloat16(vv - __bfloat162float(hv));
        }
        if (tid < 64){
            pos_y[tid] = g_pos[((size_t)bg*Npts + t*64 + tid)*2 + 0];
            pos_x[tid] = g_pos[((size_t)bg*Npts + t*64 + tid)*2 + 1];
        }
        __syncthreads();

        // ---- QK^T (bf16x3) ----
        float s[4][4];
#pragma unroll
        for (int fb=0; fb<4; fb++)
#pragma unroll
            for (int e=0; e<4; e++) s[fb][e] = 0.f;
#pragma unroll
        for (int ck = 0; ck < 4; ck++){
            const int a0 = r0*72 + ck*16 + 2*q4;
            const int a1 = r1*72 + ck*16 + 2*q4;
            uint32_t aH[4], aL[4];
            aH[0] = *(const uint32_t*)&qh[a0];   aH[1] = *(const uint32_t*)&qh[a1];
            aH[2] = *(const uint32_t*)&qh[a0+8]; aH[3] = *(const uint32_t*)&qh[a1+8];
            aL[0] = *(const uint32_t*)&ql[a0];   aL[1] = *(const uint32_t*)&ql[a1];
            aL[2] = *(const uint32_t*)&ql[a0+8]; aL[3] = *(const uint32_t*)&ql[a1+8];
#pragma unroll
            for (int fb = 0; fb < 4; fb++){
                const int kbse = (wn*32 + fb*8 + g)*72 + ck*16 + 2*q4;
                uint32_t bH0 = *(const uint32_t*)&kh[kbse];
                uint32_t bH1 = *(const uint32_t*)&kh[kbse+8];
                uint32_t bL0 = *(const uint32_t*)&kl[kbse];
                uint32_t bL1 = *(const uint32_t*)&kl[kbse+8];
                MMA_BF16(s[fb], aH[0],aH[1],aH[2],aH[3], bH0,bH1);
                MMA_BF16(s[fb], aH[0],aH[1],aH[2],aH[3], bL0,bL1);
                MMA_BF16(s[fb], aL[0],aL[1],aL[2],aL[3], bH0,bH1);
            }
        }

        // ---- scale + RPE bias in registers ----
#pragma unroll
        for (int fb=0; fb<4; fb++){
#pragma unroll
            for (int e=0; e<4; e++){
                const int nl = wn*32 + fb*8 + 2*q4 + (e&1);
                const float py = pos_y[nl], px = pos_x[nl];
                const float qyv = (e<2)? qy0 : qy1;
                const float qxv = (e<2)? qx0 : qx1;
                float gx = ((qxv-px)*0.5f + 1.f)*31.f;
                float gy = ((qyv-py)*0.5f + 1.f)*31.f;
                float x0f = floorf(gx), y0f = floorf(gy);
                float wx = gx-x0f, wy = gy-y0f;
                int x0 = max(min((int)x0f, 62), 0);
                int y0 = max(min((int)y0f, 62), 0);
                int x1 = min(x0+1, 62);
                int y1 = min(y0+1, 62);
                float rr00 = rpe_s[y0*64+x0], rr01 = rpe_s[y0*64+x1];
                float rr10 = rpe_s[y1*64+x0], rr11 = rpe_s[y1*64+x1];
                float top = rr00 + (rr01-rr00)*wx;
                float bot = rr10 + (rr11-rr10)*wx;
                s[fb][e] = s[fb][e]*0.125f + (top + (bot-top)*wy);
            }
        }

        // ---- online softmax: row max ----
        float mx0 = -1e30f, mx1 = -1e30f;
#pragma unroll
        for (int fb=0; fb<4; fb++){
            mx0 = fmaxf(mx0, fmaxf(s[fb][0], s[fb][1]));
            mx1 = fmaxf(mx1, fmaxf(s[fb][2], s[fb][3]));
        }
        mx0 = fmaxf(mx0, __shfl_xor_sync(0xffffffffu, mx0, 1));
        mx0 = fmaxf(mx0, __shfl_xor_sync(0xffffffffu, mx0, 2));
        mx1 = fmaxf(mx1, __shfl_xor_sync(0xffffffffu, mx1, 1));
        mx1 = fmaxf(mx1, __shfl_xor_sync(0xffffffffu, mx1, 2));
        if (q4 == 0){
            redmax[r0*2 + wn] = mx0;
            redmax[r1*2 + wn] = mx1;
        }
        __syncthreads();
        if (wn == 0 && q4 == 0){
#pragma unroll
            for (int rr = 0; rr < 2; rr++){
                int r = (rr==0)? r0 : r1;
                float Mold = Mrow[r];
                float mx = fmaxf(redmax[r*2], redmax[r*2+1]);
                float Mnew = fmaxf(Mold, mx);
                Arow[r] = __expf(Mold - Mnew);
                Mrow[r] = Mnew;
            }
        }
        __syncthreads();

        // ---- exp, sums, P hi/lo pack, PV mma ----
        const float Mn0 = Mrow[r0], Mn1 = Mrow[r1];
        float sum0 = 0.f, sum1 = 0.f;
#pragma unroll
        for (int fb=0; fb<4; fb++){
            s[fb][0] = __expf(s[fb][0] - Mn0); sum0 += s[fb][0];
            s[fb][1] = __expf(s[fb][1] - Mn0); sum0 += s[fb][1];
            s[fb][2] = __expf(s[fb][2] - Mn1); sum1 += s[fb][2];
            s[fb][3] = __expf(s[fb][3] - Mn1); sum1 += s[fb][3];
        }
        sum0 += __shfl_xor_sync(0xffffffffu, sum0, 1);
        sum0 += __shfl_xor_sync(0xffffffffu, sum0, 2);
        sum1 += __shfl_xor_sync(0xffffffffu, sum1, 1);
        sum1 += __shfl_xor_sync(0xffffffffu, sum1, 2);
        if (q4 == 0){
            redsum[r0*2 + wn] = sum0;
            redsum[r1*2 + wn] = sum1;
        }

        // rescale running PV accumulator
        {
            const float al0 = Arow[r0], al1 = Arow[r1];
#pragma unroll
            for (int fc=0; fc<8; fc++){
                oacc[fc][0] *= al0; oacc[fc][1] *= al0;
                oacc[fc][2] *= al1; oacc[fc][3] *= al1;
            }
        }
        // P -> A fragments (hi/lo)
#pragma unroll
        for (int ka = 0; ka < 2; ka++){
            uint32_t pH[4], pL[4];
            {
                float a = s[2*ka][0],  bb = s[2*ka][1];
                float c = s[2*ka][2],  d  = s[2*ka][3];
                float e = s[2*ka+1][0],f  = s[2*ka+1][1];
                float gv = s[2*ka+1][2],hh = s[2*ka+1][3];
                float ah_ = __bfloat162float(__float2bfloat16(a));
                float bh_ = __bfloat162float(__float2bfloat16(bb));
                float ch_ = __bfloat162float(__float2bfloat16(c));
                float dh_ = __bfloat162float(__float2bfloat16(d));
                float eh_ = __bfloat162float(__float2bfloat16(e));
                float fh_ = __bfloat162float(__float2bfloat16(f));
                float gh_ = __bfloat162float(__float2bfloat16(gv));
                float hh_ = __bfloat162float(__float2bfloat16(hh));
                pH[0] = packbf(ah_, bh_); pH[1] = packbf(ch_, dh_);
                pH[2] = packbf(eh_, fh_); pH[3] = packbf(gh_, hh_);
                pL[0] = packbf(a-ah_, bb-bh_); pL[1] = packbf(c-ch_, d-dh_);
                pL[2] = packbf(e-eh_, f-fh_);  pL[3] = packbf(gv-gh_, hh-hh_);
            }
            const int nb = wn*32 + ka*16;
#pragma unroll
            for (int fc = 0; fc < 8; fc++){
                const int vbse = (fc*8 + g)*72 + nb + 2*q4;
                uint32_t vH0 = *(const uint32_t*)&vh[vbse];
                uint32_t vH1 = *(const uint32_t*)&vh[vbse+8];
                uint32_t vL0 = *(const uint32_t*)&vl[vbse];
                uint32_t vL1 = *(const uint32_t*)&vl[vbse+8];
                MMA_BF16(oacc[fc], pH[0],pH[1],pH[2],pH[3], vH0,vH1);
                MMA_BF16(oacc[fc], pH[0],pH[1],pH[2],pH[3], vL0,vL1);
                MMA_BF16(oacc[fc], pL[0],pL[1],pL[2],pL[3], vH0,vH1);
            }
        }
        __syncthreads();
        if (wn == 0 && q4 == 0){
            Lrow[r0] = Lrow[r0]*Arow[r0] + redsum[r0*2] + redsum[r0*2+1];
            Lrow[r1] = Lrow[r1]*Arow[r1] + redsum[r1*2] + redsum[r1*2+1];
        }
    }
    __syncthreads();

    // merge wn partials + write out
    if (wn == 0){
#pragma unroll
        for (int fc=0; fc<8; fc++){
            const int c = fc*8 + 2*q4;
            outred[r0*68 + c]   = oacc[fc][0];
            outred[r0*68 + c+1] = oacc[fc][1];
            outred[r1*68 + c]   = oacc[fc][2];
            outred[r1*68 + c+1] = oacc[fc][3];
        }
    }
    __syncthreads();
    if (wn == 1){
#pragma unroll
        for (int fc=0; fc<8; fc++){
            const int c = fc*8 + 2*q4;
            outred[r0*68 + c]   += oacc[fc][0];
            outred[r0*68 + c+1] += oacc[fc][1];
            outred[r1*68 + c]   += oacc[fc][2];
            outred[r1*68 + c+1] += oacc[fc][3];
        }
    }
    __syncthreads();
    for (int i = tid; i < 64*64; i += 256){
        int c = i >> 6, m = i & 63;
        g_o[((size_t)(b*Cch + h*HC + c))*HW + m0 + m] = outred[m*68 + c] / Lrow[m];
    }
}

// ---------------------------------------------------------------------------
extern "C" void kernel_launch(void* const* d_in, const int* in_sizes, int n_in,
                              void* d_out, int out_size)
{
    const float* x   = (const float*)d_in[0];
    const float* wq  = (const float*)d_in[1];
    const float* bq  = (const float*)d_in[2];
    const float* wk  = (const float*)d_in[3];
    const float* bk  = (const float*)d_in[4];
    const float* wv  = (const float*)d_in[5];
    const float* bv  = (const float*)d_in[6];
    const float* wo  = (const float*)d_in[7];
    const float* bo  = (const float*)d_in[8];
    const float* dww = (const float*)d_in[9];
    const float* dwb = (const float*)d_in[10];
    const float* lnw = (const float*)d_in[11];
    const float* lnb = (const float*)d_in[12];
    const float* pww = (const float*)d_in[13];
    const float* rpe = (const float*)d_in[14];
    float* out = (float*)d_out;

    void *pq, *pxs, *pk, *pv, *po, *pwh, *pwl;
    cudaGetSymbolAddress(&pq,  g_q);
    cudaGetSymbolAddress(&pxs, g_xs);
    cudaGetSymbolAddress(&pk,  g_k);
    cudaGetSymbolAddress(&pv,  g_v);
    cudaGetSymbolAddress(&po,  g_o);
    cudaGetSymbolAddress(&pwh, g_wh);
    cudaGetSymbolAddress(&pwl, g_wl);
    cudaFuncSetAttribute(attn_kernel, cudaFuncAttributeMaxDynamicSharedMemorySize, 91136);
    cudaFuncSetAttribute(offset_kernel, cudaFuncAttributeMaxDynamicSharedMemorySize, 49280);

    const __nv_bfloat16* wh = (const __nv_bfloat16*)pwh;
    const __nv_bfloat16* wl = (const __nv_bfloat16*)pwl;

    const int write_pr = (out_size >= Bn*Cch*HW + 2*Bn*Gn*Npts*2) ? 1 : 0;
    float* posref = out + Bn*Cch*HW;

    const dim3 gmm(HW/128, Cch/128, Bn);
    const dim3 gtr(HW/32, Cch/32, Bn);

    convert_w<<<dim3(Cch*Cch/256, 4), 256>>>(wq, wk, wv, wo);
    trans_conv<<<gtr, 256>>>(x);
    gemm_mma<<<gmm, 256>>>(wh + 0*Cch*Cch, wl + 0*Cch*Cch, bq, (float*)pq);
    offset_kernel<<<dim3(32, Bn*Gn), 256, 49280>>>(dww, dwb, lnw, lnb, pww, posref, write_pr);
    sample_kernel<<<dim3(8, Bn*Gn), 256>>>(x);
    trans_conv<<<gtr, 256>>>((const float*)pxs);
    gemm_mma<<<gmm, 256>>>(wh + 1*Cch*Cch, wl + 1*Cch*Cch, bk, (float*)pk);
    gemm_mma<<<gmm, 256>>>(wh + 2*Cch*Cch, wl + 2*Cch*Cch, bv, (float*)pv);
    attn_kernel<<<dim3(HW/64, Bn*HEADS), 256, 91136>>>(rpe);
    trans_conv<<<gtr, 256>>>((const float*)po);
    gemm_mma<<<gmm, 256>>>(wh + 3*Cch*Cch, wl + 3*Cch*Cch, bo, out);
}

// round 9
// speedup vs baseline: 2.1821x; 1.1817x over previous
#include <cuda_runtime.h>
#include <cuda_bf16.h>
#include <cstdint>
#include <math.h>

#define Bn 4
#define Cch 512
#define HW 1024
#define HEADS 8
#define HC 64
#define Gn 4
#define GC 128
#define Npts 1024
#define RS 63

__device__ float g_q [Bn*Cch*HW];
__device__ float g_xs[Bn*Cch*Npts];
__device__ float g_k [Bn*Cch*Npts];
__device__ float g_v [Bn*Cch*Npts];
__device__ float g_o [Bn*Cch*HW];
__device__ float g_pos[Bn*Gn*Npts*2];
__device__ __nv_bfloat16 g_wh [4*Cch*Cch];
__device__ __nv_bfloat16 g_wl [4*Cch*Cch];
__device__ __nv_bfloat16 g_xth[Bn*HW*Cch];
__device__ __nv_bfloat16 g_xtl[Bn*HW*Cch];

#define MMA_BF16(d, a0,a1,a2,a3, b0,b1) \
    asm volatile("mma.sync.aligned.m16n8k16.row.col.f32.bf16.bf16.f32 " \
        "{%0,%1,%2,%3},{%4,%5,%6,%7},{%8,%9},{%0,%1,%2,%3};" \
        : "+f"((d)[0]), "+f"((d)[1]), "+f"((d)[2]), "+f"((d)[3]) \
        : "r"(a0), "r"(a1), "r"(a2), "r"(a3), "r"(b0), "r"(b1))

__device__ __forceinline__ uint32_t packbf(float a, float b){
    __nv_bfloat162 t = __floats2bfloat162_rn(a, b);
    return *(uint32_t*)&t;
}

// ---------------------------------------------------------------------------
__global__ __launch_bounds__(256) void convert_w(
    const float* __restrict__ w0, const float* __restrict__ w1,
    const float* __restrict__ w2, const float* __restrict__ w3)
{
    const int sel = blockIdx.y;
    const float* w = sel==0 ? w0 : sel==1 ? w1 : sel==2 ? w2 : w3;
    const int idx = blockIdx.x*256 + threadIdx.x;
    float v = w[idx];
    __nv_bfloat16 hi = __float2bfloat16(v);
    g_wh[sel*Cch*Cch + idx] = hi;
    g_wl[sel*Cch*Cch + idx] = __float2bfloat16(v - __bfloat162float(hi));
}

__global__ __launch_bounds__(256) void trans_conv(const float* __restrict__ X)
{
    __shared__ float tile[32][33];
    const int b = blockIdx.z;
    const int p0 = blockIdx.x*32, c0 = blockIdx.y*32;
    const int tx = threadIdx.x & 31, ty = threadIdx.x >> 5;
#pragma unroll
    for (int i = 0; i < 4; i++){
        int c = c0 + ty + i*8;
        tile[ty + i*8][tx] = X[((size_t)b*Cch + c)*HW + p0 + tx];
    }
    __syncthreads();
#pragma unroll
    for (int i = 0; i < 4; i++){
        int p = p0 + ty + i*8;
        int c = c0 + tx;
        float v = tile[tx][ty + i*8];
        __nv_bfloat16 hi = __float2bfloat16(v);
        g_xth[((size_t)b*HW + p)*Cch + c] = hi;
        g_xtl[((size_t)b*HW + p)*Cch + c] = __float2bfloat16(v - __bfloat162float(hi));
    }
}

__global__ __launch_bounds__(256) void gemm_mma(
    const __nv_bfloat16* __restrict__ Wh, const __nv_bfloat16* __restrict__ Wl,
    const float* __restrict__ bias, float* __restrict__ Y)
{
    __shared__ __nv_bfloat16 Ah_s[128][40];
    __shared__ __nv_bfloat16 Al_s[128][40];
    __shared__ __nv_bfloat16 Bh_s[128][40];
    __shared__ __nv_bfloat16 Bl_s[128][40];

    const int b  = blockIdx.z;
    const int o0 = blockIdx.y * 128;
    const int p0 = blockIdx.x * 128;
    const int tid = threadIdx.x, lane = tid & 31, wid = tid >> 5;
    const int wm = wid >> 1, wn = wid & 1;
    const int g = lane >> 2, q4 = lane & 3;

    float acc[2][8][4];
#pragma unroll
    for (int mf=0; mf<2; mf++)
#pragma unroll
        for (int nf=0; nf<8; nf++)
#pragma unroll
            for (int r=0; r<4; r++) acc[mf][nf][r] = 0.f;

    const __nv_bfloat16* wh  = Wh + (size_t)o0*Cch;
    const __nv_bfloat16* wl  = Wl + (size_t)o0*Cch;
    const __nv_bfloat16* xth = g_xth + ((size_t)b*HW + p0)*Cch;
    const __nv_bfloat16* xtl = g_xtl + ((size_t)b*HW + p0)*Cch;

    for (int kc = 0; kc < 16; kc++){
        const int k0 = kc * 32;
        __syncthreads();
#pragma unroll
        for (int i = 0; i < 8; i++){
            const int job = tid + i*256;
            const int chunk = (job & 3) * 8;
            const int row = (job >> 2) & 127;
            const int arr = job >> 9;
            const __nv_bfloat16* src;
            __nv_bfloat16* dst;
            if      (arr == 0){ src = wh  + (size_t)row*Cch + k0; dst = &Ah_s[row][0]; }
            else if (arr == 1){ src = wl  + (size_t)row*Cch + k0; dst = &Al_s[row][0]; }
            else if (arr == 2){ src = xth + (size_t)row*Cch + k0; dst = &Bh_s[row][0]; }
            else              { src = xtl + (size_t)row*Cch + k0; dst = &Bl_s[row][0]; }
            *(uint4*)(dst + chunk) = *(const uint4*)(src + chunk);
        }
        __syncthreads();

#pragma unroll
        for (int k16 = 0; k16 < 2; k16++){
            const int kb = k16*16 + q4*2;
            uint32_t ah[2][4], al[2][4];
#pragma unroll
            for (int mf=0; mf<2; mf++){
                const int r = wm*32 + mf*16 + g;
                ah[mf][0] = *(const uint32_t*)&Ah_s[r  ][kb];
                ah[mf][1] = *(const uint32_t*)&Ah_s[r+8][kb];
                ah[mf][2] = *(const uint32_t*)&Ah_s[r  ][kb+8];
                ah[mf][3] = *(const uint32_t*)&Ah_s[r+8][kb+8];
                al[mf][0] = *(const uint32_t*)&Al_s[r  ][kb];
                al[mf][1] = *(const uint32_t*)&Al_s[r+8][kb];
                al[mf][2] = *(const uint32_t*)&Al_s[r  ][kb+8];
                al[mf][3] = *(const uint32_t*)&Al_s[r+8][kb+8];
            }
#pragma unroll
            for (int nf=0; nf<8; nf++){
                const int n = wn*64 + nf*8 + g;
                const uint32_t bh0 = *(const uint32_t*)&Bh_s[n][kb];
                const uint32_t bh1 = *(const uint32_t*)&Bh_s[n][kb+8];
                const uint32_t bl0 = *(const uint32_t*)&Bl_s[n][kb];
                const uint32_t bl1 = *(const uint32_t*)&Bl_s[n][kb+8];
#pragma unroll
                for (int mf=0; mf<2; mf++){
                    MMA_BF16(acc[mf][nf], ah[mf][0],ah[mf][1],ah[mf][2],ah[mf][3], bh0,bh1);
                    MMA_BF16(acc[mf][nf], ah[mf][0],ah[mf][1],ah[mf][2],ah[mf][3], bl0,bl1);
                    MMA_BF16(acc[mf][nf], al[mf][0],al[mf][1],al[mf][2],al[mf][3], bh0,bh1);
                }
            }
        }
    }

#pragma unroll
    for (int mf=0; mf<2; mf++){
        const int o = o0 + wm*32 + mf*16 + g;
        const float bv0 = bias[o], bv8 = bias[o+8];
#pragma unroll
        for (int nf=0; nf<8; nf++){
            const int p = p0 + wn*64 + nf*8 + q4*2;
            float2 lo2, hi2;
            lo2.x = acc[mf][nf][0] + bv0; lo2.y = acc[mf][nf][1] + bv0;
            hi2.x = acc[mf][nf][2] + bv8; hi2.y = acc[mf][nf][3] + bv8;
            *(float2*)(Y + ((size_t)b*Cch + o  )*HW + p) = lo2;
            *(float2*)(Y + ((size_t)b*Cch + o+8)*HW + p) = hi2;
        }
    }
}

// ---------------------------------------------------------------------------
// Offset network v3: block=(row y, bg); tid = x*8+g; thread owns 16 channels
// (ch=j*8+g) of pixel x. All reductions are 3 shfl_xor; no barriers after
// staging. Dyn smem: 3*32*136 + 1152 + 3*128 + 256 = 14848 f = 59392 B.
// ---------------------------------------------------------------------------
__global__ __launch_bounds__(256) void offset_kernel(
    const float* __restrict__ dw_w, const float* __restrict__ dw_b,
    const float* __restrict__ ln_w, const float* __restrict__ ln_b,
    const float* __restrict__ pw_w, float* __restrict__ posref, int write_pr)
{
    extern __shared__ float osm[];
    float* qs   = osm;              // [3][32][136]
    float* dws  = qs + 13056;       // [9][128]
    float* dwbs = dws + 1152;       // 128
    float* lnws = dwbs + 128;       // 128
    float* lnbs = lnws + 128;       // 128
    float* pws  = lnbs + 128;       // [2][128]

    const int y  = blockIdx.x;       // 0..31
    const int bg = blockIdx.y;       // 0..15
    const int tid = threadIdx.x;
    const int x = tid >> 3;          // pixel column 0..31
    const int g = tid & 7;           // channel slice
    const int b = bg >> 2, gr = bg & 3;

    // stage 3 q-rows, all 128 channels (coalesced reads)
    for (int i = tid; i < 3*128*32; i += 256){
        int r = i >> 12, rem = i & 4095;
        int cl = rem >> 5, xx = rem & 31;
        int yy = y - 1 + r;
        float val = 0.f;
        if (yy >= 0 && yy < 32)
            val = g_q[((size_t)(b*Cch + gr*GC + cl))*HW + yy*32 + xx];
        qs[(r*32 + xx)*136 + cl] = val;
    }
    // stage weights
    for (int i = tid; i < 1152; i += 256){
        int ch = i / 9, k = i - ch*9;
        dws[k*128 + ch] = dw_w[i];
    }
    if (tid < 128){
        dwbs[tid] = dw_b[tid];
        lnws[tid] = ln_w[tid];
        lnbs[tid] = ln_b[tid];
        pws[tid]       = pw_w[tid];
        pws[128 + tid] = pw_w[128 + tid];
    }
    __syncthreads();

    const bool rv0 = (y-1 >= 0), rv2 = (y+1 < 32);

    float v[16];
#pragma unroll
    for (int j = 0; j < 16; j++){
        const int ch = j*8 + g;
        float acc = dwbs[ch];
#pragma unroll
        for (int ky = 0; ky < 3; ky++){
            if (ky == 0 && !rv0) continue;
            if (ky == 2 && !rv2) continue;
#pragma unroll
            for (int kx = 0; kx < 3; kx++){
                const int xx = x + kx - 1;
                if (xx < 0 || xx > 31) continue;
                acc += qs[(ky*32 + xx)*136 + ch] * dws[(ky*3 + kx)*128 + ch];
            }
        }
        v[j] = acc;
    }
    // mean over 128 channels (16 local + 8-lane shfl group)
    float m = 0.f;
#pragma unroll
    for (int j = 0; j < 16; j++) m += v[j];
    m += __shfl_xor_sync(0xffffffffu, m, 1);
    m += __shfl_xor_sync(0xffffffffu, m, 2);
    m += __shfl_xor_sync(0xffffffffu, m, 4);
    m *= (1.f/128.f);
    // variance
    float var = 0.f;
#pragma unroll
    for (int j = 0; j < 16; j++){ float d = v[j] - m; var += d*d; }
    var += __shfl_xor_sync(0xffffffffu, var, 1);
    var += __shfl_xor_sync(0xffffffffu, var, 2);
    var += __shfl_xor_sync(0xffffffffu, var, 4);
    var *= (1.f/128.f);
    const float rstd = rsqrtf(var + 1e-5f);
    // LN + GELU + projection
    float s0 = 0.f, s1 = 0.f;
#pragma unroll
    for (int j = 0; j < 16; j++){
        const int ch = j*8 + g;
        float o = (v[j] - m)*rstd*lnws[ch] + lnbs[ch];
        o = 0.5f * o * (1.f + erff(o * 0.70710678118654752440f));
        s0 += o * pws[ch];
        s1 += o * pws[128 + ch];
    }
    s0 += __shfl_xor_sync(0xffffffffu, s0, 1);
    s0 += __shfl_xor_sync(0xffffffffu, s0, 2);
    s0 += __shfl_xor_sync(0xffffffffu, s0, 4);
    s1 += __shfl_xor_sync(0xffffffffu, s1, 1);
    s1 += __shfl_xor_sync(0xffffffffu, s1, 2);
    s1 += __shfl_xor_sync(0xffffffffu, s1, 4);

    if (g == 0){
        float ry = ((y+0.5f)/31.f)*2.f - 1.f;
        float rx = ((x+0.5f)/31.f)*2.f - 1.f;
        float py = fminf(fmaxf(s0 + ry, -1.f), 1.f);
        float px = fminf(fmaxf(s1 + rx, -1.f), 1.f);
        int idx = (bg*Npts + y*32 + x)*2;
        g_pos[idx+0] = py;
        g_pos[idx+1] = px;
        if (write_pr){
            posref[idx+0] = py;
            posref[idx+1] = px;
            posref[Bn*Gn*Npts*2 + idx + 0] = ry;
            posref[Bn*Gn*Npts*2 + idx + 1] = rx;
        }
    }
}

// ---------------------------------------------------------------------------
__global__ __launch_bounds__(256) void sample_kernel(const float* __restrict__ x)
{
    const int cc = blockIdx.x;
    const int bg = blockIdx.y;
    const int b = bg >> 2, g = bg & 3;
    for (int n = threadIdx.x; n < Npts; n += 256){
        float py = g_pos[(bg*Npts+n)*2+0];
        float px = g_pos[(bg*Npts+n)*2+1];
        float gx = (px+1.f)*0.5f*31.f;
        float gy = (py+1.f)*0.5f*31.f;
        float x0f = floorf(gx), y0f = floorf(gy);
        float wx = gx-x0f, wy = gy-y0f;
        int x0 = max(min((int)x0f, 31), 0);
        int y0 = max(min((int)y0f, 31), 0);
        int x1 = min(x0+1, 31);
        int y1 = min(y0+1, 31);
        float w00 = (1.f-wx)*(1.f-wy), w10 = wx*(1.f-wy);
        float w01 = (1.f-wx)*wy,       w11 = wx*wy;
        for (int cj = 0; cj < 16; cj++){
            int cfull = g*GC + cc*16 + cj;
            const float* pl = x + ((size_t)(b*Cch + cfull))*HW;
            float val = pl[y0*32+x0]*w00 + pl[y0*32+x1]*w10
                      + pl[y1*32+x0]*w01 + pl[y1*32+x1]*w11;
            g_xs[((size_t)(b*Cch + cfull))*Npts + n] = val;
        }
    }
}

// ---------------------------------------------------------------------------
// Fused attention v4: tensor-core bf16x3 flash attention (unchanged from R8).
// ---------------------------------------------------------------------------
__global__ __launch_bounds__(256) void attn_kernel(const float* __restrict__ rpe)
{
    extern __shared__ char smraw[];
    float* rpe_s  = (float*)smraw;          // 4032
    float* pos_y  = rpe_s + 4032;           // 64
    float* pos_x  = pos_y + 64;             // 64
    float* Mrow   = pos_x + 64;             // 64
    float* Lrow   = Mrow + 64;              // 64
    float* Arow   = Lrow + 64;              // 64
    float* redmax = Arow + 64;              // 128
    float* redsum = redmax + 128;           // 128
    float* outred = redsum + 128;           // 4352
    __nv_bfloat16* qh = (__nv_bfloat16*)(outred + 4352);
    __nv_bfloat16* ql = qh + 64*72;
    __nv_bfloat16* kh = ql + 64*72;
    __nv_bfloat16* kl = kh + 64*72;
    __nv_bfloat16* vh = kl + 64*72;
    __nv_bfloat16* vl = vh + 64*72;

    const int tid = threadIdx.x;
    const int bh = blockIdx.y;
    const int m0 = blockIdx.x * 64;
    const int b = bh >> 3, h = bh & 7, gg = h >> 1;
    const int lane = tid & 31, wid = tid >> 5;
    const int wm = wid & 3, wn = wid >> 2;
    const int g = lane >> 2, q4 = lane & 3;
    const int bg = b*Gn + gg;

    const float* rh = rpe + (size_t)h*RS*RS;
    for (int i = tid; i < RS*RS; i += 256) rpe_s[(i/RS)*64 + (i%RS)] = rh[i];

    const float* qb = g_q + ((size_t)(b*Cch + h*HC))*HW + m0;
    for (int i = tid; i < 64*64; i += 256){
        int c = i >> 6, m = i & 63;
        float qv = qb[(size_t)c*HW + m];
        __nv_bfloat16 hi = __float2bfloat16(qv);
        qh[m*72 + c] = hi;
        ql[m*72 + c] = __float2bfloat16(qv - __bfloat162float(hi));
    }
    if (tid < 64){ Mrow[tid] = -1e30f; Lrow[tid] = 0.f; }

    const int r0 = wm*16 + g, r1 = r0 + 8;
    const int mg0 = m0 + r0, mg1 = m0 + r1;
    const float qy0 = (float)(mg0>>5)*(2.f/31.f) - 1.f;
    const float qx0 = (float)(mg0&31)*(2.f/31.f) - 1.f;
    const float qy1 = (float)(mg1>>5)*(2.f/31.f) - 1.f;
    const float qx1 = (float)(mg1&31)*(2.f/31.f) - 1.f;

    const float* kb = g_k + ((size_t)(b*Cch + h*HC))*Npts;
    const float* vb = g_v + ((size_t)(b*Cch + h*HC))*Npts;

    float oacc[8][4];
#pragma unroll
    for (int fc=0; fc<8; fc++)
#pragma unroll
        for (int e=0; e<4; e++) oacc[fc][e] = 0.f;

    for (int t = 0; t < 16; t++){
        for (int i = tid; i < 64*64; i += 256){
            int c = i >> 6, n = i & 63;
            float kv = kb[(size_t)c*Npts + t*64 + n];
            __nv_bfloat16 hk = __float2bfloat16(kv);
            kh[n*72 + c] = hk;
            kl[n*72 + c] = __float2bfloat16(kv - __bfloat162float(hk));
            float vv = vb[(size_t)c*Npts + t*64 + n];
            __nv_bfloat16 hv = __float2bfloat16(vv);
            vh[c*72 + n] = hv;
            vl[c*72 + n] = __float2bfloat16(vv - __bfloat162float(hv));
        }
        if (tid < 64){
            pos_y[tid] = g_pos[((size_t)bg*Npts + t*64 + tid)*2 + 0];
            pos_x[tid] = g_pos[((size_t)bg*Npts + t*64 + tid)*2 + 1];
        }
        __syncthreads();

        float s[4][4];
#pragma unroll
        for (int fb=0; fb<4; fb++)
#pragma unroll
            for (int e=0; e<4; e++) s[fb][e] = 0.f;
#pragma unroll
        for (int ck = 0; ck < 4; ck++){
            const int a0 = r0*72 + ck*16 + 2*q4;
            const int a1 = r1*72 + ck*16 + 2*q4;
            uint32_t aH[4], aL[4];
            aH[0] = *(const uint32_t*)&qh[a0];   aH[1] = *(const uint32_t*)&qh[a1];
            aH[2] = *(const uint32_t*)&qh[a0+8]; aH[3] = *(const uint32_t*)&qh[a1+8];
            aL[0] = *(const uint32_t*)&ql[a0];   aL[1] = *(const uint32_t*)&ql[a1];
            aL[2] = *(const uint32_t*)&ql[a0+8]; aL[3] = *(const uint32_t*)&ql[a1+8];
#pragma unroll
            for (int fb = 0; fb < 4; fb++){
                const int kbse = (wn*32 + fb*8 + g)*72 + ck*16 + 2*q4;
                uint32_t bH0 = *(const uint32_t*)&kh[kbse];
                uint32_t bH1 = *(const uint32_t*)&kh[kbse+8];
                uint32_t bL0 = *(const uint32_t*)&kl[kbse];
                uint32_t bL1 = *(const uint32_t*)&kl[kbse+8];
                MMA_BF16(s[fb], aH[0],aH[1],aH[2],aH[3], bH0,bH1);
                MMA_BF16(s[fb], aH[0],aH[1],aH[2],aH[3], bL0,bL1);
                MMA_BF16(s[fb], aL[0],aL[1],aL[2],aL[3], bH0,bH1);
            }
        }

#pragma unroll
        for (int fb=0; fb<4; fb++){
#pragma unroll
            for (int e=0; e<4; e++){
                const int nl = wn*32 + fb*8 + 2*q4 + (e&1);
                const float py = pos_y[nl], px = pos_x[nl];
                const float qyv = (e<2)? qy0 : qy1;
                const float qxv = (e<2)? qx0 : qx1;
                float gx = ((qxv-px)*0.5f + 1.f)*31.f;
                float gy = ((qyv-py)*0.5f + 1.f)*31.f;
                float x0f = floorf(gx), y0f = floorf(gy);
                float wx = gx-x0f, wy = gy-y0f;
                int x0 = max(min((int)x0f, 62), 0);
                int y0 = max(min((int)y0f, 62), 0);
                int x1 = min(x0+1, 62);
                int y1 = min(y0+1, 62);
                float rr00 = rpe_s[y0*64+x0], rr01 = rpe_s[y0*64+x1];
                float rr10 = rpe_s[y1*64+x0], rr11 = rpe_s[y1*64+x1];
                float top = rr00 + (rr01-rr00)*wx;
                float bot = rr10 + (rr11-rr10)*wx;
                s[fb][e] = s[fb][e]*0.125f + (top + (bot-top)*wy);
            }
        }

        float mx0 = -1e30f, mx1 = -1e30f;
#pragma unroll
        for (int fb=0; fb<4; fb++){
            mx0 = fmaxf(mx0, fmaxf(s[fb][0], s[fb][1]));
            mx1 = fmaxf(mx1, fmaxf(s[fb][2], s[fb][3]));
        }
        mx0 = fmaxf(mx0, __shfl_xor_sync(0xffffffffu, mx0, 1));
        mx0 = fmaxf(mx0, __shfl_xor_sync(0xffffffffu, mx0, 2));
        mx1 = fmaxf(mx1, __shfl_xor_sync(0xffffffffu, mx1, 1));
        mx1 = fmaxf(mx1, __shfl_xor_sync(0xffffffffu, mx1, 2));
        if (q4 == 0){
            redmax[r0*2 + wn] = mx0;
            redmax[r1*2 + wn] = mx1;
        }
        __syncthreads();
        if (wn == 0 && q4 == 0){
#pragma unroll
            for (int rr = 0; rr < 2; rr++){
                int r = (rr==0)? r0 : r1;
                float Mold = Mrow[r];
                float mx = fmaxf(redmax[r*2], redmax[r*2+1]);
                float Mnew = fmaxf(Mold, mx);
                Arow[r] = __expf(Mold - Mnew);
                Mrow[r] = Mnew;
            }
        }
        __syncthreads();

        const float Mn0 = Mrow[r0], Mn1 = Mrow[r1];
        float sum0 = 0.f, sum1 = 0.f;
#pragma unroll
        for (int fb=0; fb<4; fb++){
            s[fb][0] = __expf(s[fb][0] - Mn0); sum0 += s[fb][0];
            s[fb][1] = __expf(s[fb][1] - Mn0); sum0 += s[fb][1];
            s[fb][2] = __expf(s[fb][2] - Mn1); sum1 += s[fb][2];
            s[fb][3] = __expf(s[fb][3] - Mn1); sum1 += s[fb][3];
        }
        sum0 += __shfl_xor_sync(0xffffffffu, sum0, 1);
        sum0 += __shfl_xor_sync(0xffffffffu, sum0, 2);
        sum1 += __shfl_xor_sync(0xffffffffu, sum1, 1);
        sum1 += __shfl_xor_sync(0xffffffffu, sum1, 2);
        if (q4 == 0){
            redsum[r0*2 + wn] = sum0;
            redsum[r1*2 + wn] = sum1;
        }

        {
            const float al0 = Arow[r0], al1 = Arow[r1];
#pragma unroll
            for (int fc=0; fc<8; fc++){
                oacc[fc][0] *= al0; oacc[fc][1] *= al0;
                oacc[fc][2] *= al1; oacc[fc][3] *= al1;
            }
        }
#pragma unroll
        for (int ka = 0; ka < 2; ka++){
            uint32_t pH[4], pL[4];
            {
                float a = s[2*ka][0],  bb = s[2*ka][1];
                float c = s[2*ka][2],  d  = s[2*ka][3];
                float e = s[2*ka+1][0],f  = s[2*ka+1][1];
                float gv = s[2*ka+1][2],hh = s[2*ka+1][3];
                float ah_ = __bfloat162float(__float2bfloat16(a));
                float bh_ = __bfloat162float(__float2bfloat16(bb));
                float ch_ = __bfloat162float(__float2bfloat16(c));
                float dh_ = __bfloat162float(__float2bfloat16(d));
                float eh_ = __bfloat162float(__float2bfloat16(e));
                float fh_ = __bfloat162float(__float2bfloat16(f));
                float gh_ = __bfloat162float(__float2bfloat16(gv));
                float hh_ = __bfloat162float(__float2bfloat16(hh));
                pH[0] = packbf(ah_, bh_); pH[1] = packbf(ch_, dh_);
                pH[2] = packbf(eh_, fh_); pH[3] = packbf(gh_, hh_);
                pL[0] = packbf(a-ah_, bb-bh_); pL[1] = packbf(c-ch_, d-dh_);
                pL[2] = packbf(e-eh_, f-fh_);  pL[3] = packbf(gv-gh_, hh-hh_);
            }
            const int nb = wn*32 + ka*16;
#pragma unroll
            for (int fc = 0; fc < 8; fc++){
                const int vbse = (fc*8 + g)*72 + nb + 2*q4;
                uint32_t vH0 = *(const uint32_t*)&vh[vbse];
                uint32_t vH1 = *(const uint32_t*)&vh[vbse+8];
                uint32_t vL0 = *(const uint32_t*)&vl[vbse];
                uint32_t vL1 = *(const uint32_t*)&vl[vbse+8];
                MMA_BF16(oacc[fc], pH[0],pH[1],pH[2],pH[3], vH0,vH1);
                MMA_BF16(oacc[fc], pH[0],pH[1],pH[2],pH[3], vL0,vL1);
                MMA_BF16(oacc[fc], pL[0],pL[1],pL[2],pL[3], vH0,vH1);
            }
        }
        __syncthreads();
        if (wn == 0 && q4 == 0){
            Lrow[r0] = Lrow[r0]*Arow[r0] + redsum[r0*2] + redsum[r0*2+1];
            Lrow[r1] = Lrow[r1]*Arow[r1] + redsum[r1*2] + redsum[r1*2+1];
        }
    }
    __syncthreads();

    if (wn == 0){
#pragma unroll
        for (int fc=0; fc<8; fc++){
            const int c = fc*8 + 2*q4;
            outred[r0*68 + c]   = oacc[fc][0];
            outred[r0*68 + c+1] = oacc[fc][1];
            outred[r1*68 + c]   = oacc[fc][2];
            outred[r1*68 + c+1] = oacc[fc][3];
        }
    }
    __syncthreads();
    if (wn == 1){
#pragma unroll
        for (int fc=0; fc<8; fc++){
            const int c = fc*8 + 2*q4;
            outred[r0*68 + c]   += oacc[fc][0];
            outred[r0*68 + c+1] += oacc[fc][1];
            outred[r1*68 + c]   += oacc[fc][2];
            outred[r1*68 + c+1] += oacc[fc][3];
        }
    }
    __syncthreads();
    for (int i = tid; i < 64*64; i += 256){
        int c = i >> 6, m = i & 63;
        g_o[((size_t)(b*Cch + h*HC + c))*HW + m0 + m] = outred[m*68 + c] / Lrow[m];
    }
}

// ---------------------------------------------------------------------------
extern "C" void kernel_launch(void* const* d_in, const int* in_sizes, int n_in,
                              void* d_out, int out_size)
{
    const float* x   = (const float*)d_in[0];
    const float* wq  = (const float*)d_in[1];
    const float* bq  = (const float*)d_in[2];
    const float* wk  = (const float*)d_in[3];
    const float* bk  = (const float*)d_in[4];
    const float* wv  = (const float*)d_in[5];
    const float* bv  = (const float*)d_in[6];
    const float* wo  = (const float*)d_in[7];
    const float* bo  = (const float*)d_in[8];
    const float* dww = (const float*)d_in[9];
    const float* dwb = (const float*)d_in[10];
    const float* lnw = (const float*)d_in[11];
    const float* lnb = (const float*)d_in[12];
    const float* pww = (const float*)d_in[13];
    const float* rpe = (const float*)d_in[14];
    float* out = (float*)d_out;

    void *pq, *pxs, *pk, *pv, *po, *pwh, *pwl;
    cudaGetSymbolAddress(&pq,  g_q);
    cudaGetSymbolAddress(&pxs, g_xs);
    cudaGetSymbolAddress(&pk,  g_k);
    cudaGetSymbolAddress(&pv,  g_v);
    cudaGetSymbolAddress(&po,  g_o);
    cudaGetSymbolAddress(&pwh, g_wh);
    cudaGetSymbolAddress(&pwl, g_wl);
    cudaFuncSetAttribute(attn_kernel, cudaFuncAttributeMaxDynamicSharedMemorySize, 91136);
    cudaFuncSetAttribute(offset_kernel, cudaFuncAttributeMaxDynamicSharedMemorySize, 59392);

    const __nv_bfloat16* wh = (const __nv_bfloat16*)pwh;
    const __nv_bfloat16* wl = (const __nv_bfloat16*)pwl;

    const int write_pr = (out_size >= Bn*Cch*HW + 2*Bn*Gn*Npts*2) ? 1 : 0;
    float* posref = out + Bn*Cch*HW;

    const dim3 gmm(HW/128, Cch/128, Bn);
    const dim3 gtr(HW/32, Cch/32, Bn);

    convert_w<<<dim3(Cch*Cch/256, 4), 256>>>(wq, wk, wv, wo);
    trans_conv<<<gtr, 256>>>(x);
    gemm_mma<<<gmm, 256>>>(wh + 0*Cch*Cch, wl + 0*Cch*Cch, bq, (float*)pq);
    offset_kernel<<<dim3(32, Bn*Gn), 256, 59392>>>(dww, dwb, lnw, lnb, pww, posref, write_pr);
    sample_kernel<<<dim3(8, Bn*Gn), 256>>>(x);
    trans_conv<<<gtr, 256>>>((const float*)pxs);
    gemm_mma<<<gmm, 256>>>(wh + 1*Cch*Cch, wl + 1*Cch*Cch, bk, (float*)pk);
    gemm_mma<<<gmm, 256>>>(wh + 2*Cch*Cch, wl + 2*Cch*Cch, bv, (float*)pv);
    attn_kernel<<<dim3(HW/64, Bn*HEADS), 256, 91136>>>(rpe);
    trans_conv<<<gtr, 256>>>((const float*)po);
    gemm_mma<<<gmm, 256>>>(wh + 3*Cch*Cch, wl + 3*Cch*Cch, bo, out);
}

// round 10
// speedup vs baseline: 2.4412x; 1.1187x over previous
#include <cuda_runtime.h>
#include <cuda_bf16.h>
#include <cstdint>
#include <math.h>

#define Bn 4
#define Cch 512
#define HW 1024
#define HEADS 8
#define HC 64
#define Gn 4
#define GC 128
#define Npts 1024
#define RS 63

__device__ float g_q [Bn*Cch*HW];
__device__ float g_xs[Bn*Cch*Npts];
__device__ float g_k [Bn*Cch*Npts];
__device__ float g_v [Bn*Cch*Npts];
__device__ float g_pos[Bn*Gn*Npts*2];
__device__ __nv_bfloat16 g_wh [4*Cch*Cch];
__device__ __nv_bfloat16 g_wl [4*Cch*Cch];
__device__ __nv_bfloat16 g_xth[Bn*HW*Cch];
__device__ __nv_bfloat16 g_xtl[Bn*HW*Cch];

#define MMA_BF16(d, a0,a1,a2,a3, b0,b1) \
    asm volatile("mma.sync.aligned.m16n8k16.row.col.f32.bf16.bf16.f32 " \
        "{%0,%1,%2,%3},{%4,%5,%6,%7},{%8,%9},{%0,%1,%2,%3};" \
        : "+f"((d)[0]), "+f"((d)[1]), "+f"((d)[2]), "+f"((d)[3]) \
        : "r"(a0), "r"(a1), "r"(a2), "r"(a3), "r"(b0), "r"(b1))

__device__ __forceinline__ uint32_t packbf(float a, float b){
    __nv_bfloat162 t = __floats2bfloat162_rn(a, b);
    return *(uint32_t*)&t;
}

// ---------------------------------------------------------------------------
__global__ __launch_bounds__(256) void convert_w(
    const float* __restrict__ w0, const float* __restrict__ w1,
    const float* __restrict__ w2, const float* __restrict__ w3)
{
    const int sel = blockIdx.y;
    const float* w = sel==0 ? w0 : sel==1 ? w1 : sel==2 ? w2 : w3;
    const int idx = blockIdx.x*256 + threadIdx.x;
    float v = w[idx];
    __nv_bfloat16 hi = __float2bfloat16(v);
    g_wh[sel*Cch*Cch + idx] = hi;
    g_wl[sel*Cch*Cch + idx] = __float2bfloat16(v - __bfloat162float(hi));
}

__global__ __launch_bounds__(256) void trans_conv(const float* __restrict__ X)
{
    __shared__ float tile[32][33];
    const int b = blockIdx.z;
    const int p0 = blockIdx.x*32, c0 = blockIdx.y*32;
    const int tx = threadIdx.x & 31, ty = threadIdx.x >> 5;
#pragma unroll
    for (int i = 0; i < 4; i++){
        int c = c0 + ty + i*8;
        tile[ty + i*8][tx] = X[((size_t)b*Cch + c)*HW + p0 + tx];
    }
    __syncthreads();
#pragma unroll
    for (int i = 0; i < 4; i++){
        int p = p0 + ty + i*8;
        int c = c0 + tx;
        float v = tile[tx][ty + i*8];
        __nv_bfloat16 hi = __float2bfloat16(v);
        g_xth[((size_t)b*HW + p)*Cch + c] = hi;
        g_xtl[((size_t)b*HW + p)*Cch + c] = __float2bfloat16(v - __bfloat162float(hi));
    }
}

__global__ __launch_bounds__(256) void gemm_mma(
    const __nv_bfloat16* __restrict__ Wh, const __nv_bfloat16* __restrict__ Wl,
    const float* __restrict__ bias, float* __restrict__ Y)
{
    __shared__ __nv_bfloat16 Ah_s[128][40];
    __shared__ __nv_bfloat16 Al_s[128][40];
    __shared__ __nv_bfloat16 Bh_s[128][40];
    __shared__ __nv_bfloat16 Bl_s[128][40];

    const int b  = blockIdx.z;
    const int o0 = blockIdx.y * 128;
    const int p0 = blockIdx.x * 128;
    const int tid = threadIdx.x, lane = tid & 31, wid = tid >> 5;
    const int wm = wid >> 1, wn = wid & 1;
    const int g = lane >> 2, q4 = lane & 3;

    float acc[2][8][4];
#pragma unroll
    for (int mf=0; mf<2; mf++)
#pragma unroll
        for (int nf=0; nf<8; nf++)
#pragma unroll
            for (int r=0; r<4; r++) acc[mf][nf][r] = 0.f;

    const __nv_bfloat16* wh  = Wh + (size_t)o0*Cch;
    const __nv_bfloat16* wl  = Wl + (size_t)o0*Cch;
    const __nv_bfloat16* xth = g_xth + ((size_t)b*HW + p0)*Cch;
    const __nv_bfloat16* xtl = g_xtl + ((size_t)b*HW + p0)*Cch;

    for (int kc = 0; kc < 16; kc++){
        const int k0 = kc * 32;
        __syncthreads();
#pragma unroll
        for (int i = 0; i < 8; i++){
            const int job = tid + i*256;
            const int chunk = (job & 3) * 8;
            const int row = (job >> 2) & 127;
            const int arr = job >> 9;
            const __nv_bfloat16* src;
            __nv_bfloat16* dst;
            if      (arr == 0){ src = wh  + (size_t)row*Cch + k0; dst = &Ah_s[row][0]; }
            else if (arr == 1){ src = wl  + (size_t)row*Cch + k0; dst = &Al_s[row][0]; }
            else if (arr == 2){ src = xth + (size_t)row*Cch + k0; dst = &Bh_s[row][0]; }
            else              { src = xtl + (size_t)row*Cch + k0; dst = &Bl_s[row][0]; }
            *(uint4*)(dst + chunk) = *(const uint4*)(src + chunk);
        }
        __syncthreads();

#pragma unroll
        for (int k16 = 0; k16 < 2; k16++){
            const int kb = k16*16 + q4*2;
            uint32_t ah[2][4], al[2][4];
#pragma unroll
            for (int mf=0; mf<2; mf++){
                const int r = wm*32 + mf*16 + g;
                ah[mf][0] = *(const uint32_t*)&Ah_s[r  ][kb];
                ah[mf][1] = *(const uint32_t*)&Ah_s[r+8][kb];
                ah[mf][2] = *(const uint32_t*)&Ah_s[r  ][kb+8];
                ah[mf][3] = *(const uint32_t*)&Ah_s[r+8][kb+8];
                al[mf][0] = *(const uint32_t*)&Al_s[r  ][kb];
                al[mf][1] = *(const uint32_t*)&Al_s[r+8][kb];
                al[mf][2] = *(const uint32_t*)&Al_s[r  ][kb+8];
                al[mf][3] = *(const uint32_t*)&Al_s[r+8][kb+8];
            }
#pragma unroll
            for (int nf=0; nf<8; nf++){
                const int n = wn*64 + nf*8 + g;
                const uint32_t bh0 = *(const uint32_t*)&Bh_s[n][kb];
                const uint32_t bh1 = *(const uint32_t*)&Bh_s[n][kb+8];
                const uint32_t bl0 = *(const uint32_t*)&Bl_s[n][kb];
                const uint32_t bl1 = *(const uint32_t*)&Bl_s[n][kb+8];
#pragma unroll
                for (int mf=0; mf<2; mf++){
                    MMA_BF16(acc[mf][nf], ah[mf][0],ah[mf][1],ah[mf][2],ah[mf][3], bh0,bh1);
                    MMA_BF16(acc[mf][nf], ah[mf][0],ah[mf][1],ah[mf][2],ah[mf][3], bl0,bl1);
                    MMA_BF16(acc[mf][nf], al[mf][0],al[mf][1],al[mf][2],al[mf][3], bh0,bh1);
                }
            }
        }
    }

#pragma unroll
    for (int mf=0; mf<2; mf++){
        const int o = o0 + wm*32 + mf*16 + g;
        const float bv0 = bias[o], bv8 = bias[o+8];
#pragma unroll
        for (int nf=0; nf<8; nf++){
            const int p = p0 + wn*64 + nf*8 + q4*2;
            float2 lo2, hi2;
            lo2.x = acc[mf][nf][0] + bv0; lo2.y = acc[mf][nf][1] + bv0;
            hi2.x = acc[mf][nf][2] + bv8; hi2.y = acc[mf][nf][3] + bv8;
            *(float2*)(Y + ((size_t)b*Cch + o  )*HW + p) = lo2;
            *(float2*)(Y + ((size_t)b*Cch + o+8)*HW + p) = hi2;
        }
    }
}

// ---------------------------------------------------------------------------
// Offset network v3 (unchanged from R9).
// ---------------------------------------------------------------------------
__global__ __launch_bounds__(256) void offset_kernel(
    const float* __restrict__ dw_w, const float* __restrict__ dw_b,
    const float* __restrict__ ln_w, const float* __restrict__ ln_b,
    const float* __restrict__ pw_w, float* __restrict__ posref, int write_pr)
{
    extern __shared__ float osm[];
    float* qs   = osm;              // [3][32][136]
    float* dws  = qs + 13056;       // [9][128]
    float* dwbs = dws + 1152;
    float* lnws = dwbs + 128;
    float* lnbs = lnws + 128;
    float* pws  = lnbs + 128;       // [2][128]

    const int y  = blockIdx.x;
    const int bg = blockIdx.y;
    const int tid = threadIdx.x;
    const int x = tid >> 3;
    const int g = tid & 7;
    const int b = bg >> 2, gr = bg & 3;

    for (int i = tid; i < 3*128*32; i += 256){
        int r = i >> 12, rem = i & 4095;
        int cl = rem >> 5, xx = rem & 31;
        int yy = y - 1 + r;
        float val = 0.f;
        if (yy >= 0 && yy < 32)
            val = g_q[((size_t)(b*Cch + gr*GC + cl))*HW + yy*32 + xx];
        qs[(r*32 + xx)*136 + cl] = val;
    }
    for (int i = tid; i < 1152; i += 256){
        int ch = i / 9, k = i - ch*9;
        dws[k*128 + ch] = dw_w[i];
    }
    if (tid < 128){
        dwbs[tid] = dw_b[tid];
        lnws[tid] = ln_w[tid];
        lnbs[tid] = ln_b[tid];
        pws[tid]       = pw_w[tid];
        pws[128 + tid] = pw_w[128 + tid];
    }
    __syncthreads();

    const bool rv0 = (y-1 >= 0), rv2 = (y+1 < 32);

    float v[16];
#pragma unroll
    for (int j = 0; j < 16; j++){
        const int ch = j*8 + g;
        float acc = dwbs[ch];
#pragma unroll
        for (int ky = 0; ky < 3; ky++){
            if (ky == 0 && !rv0) continue;
            if (ky == 2 && !rv2) continue;
#pragma unroll
            for (int kx = 0; kx < 3; kx++){
                const int xx = x + kx - 1;
                if (xx < 0 || xx > 31) continue;
                acc += qs[(ky*32 + xx)*136 + ch] * dws[(ky*3 + kx)*128 + ch];
            }
        }
        v[j] = acc;
    }
    float m = 0.f;
#pragma unroll
    for (int j = 0; j < 16; j++) m += v[j];
    m += __shfl_xor_sync(0xffffffffu, m, 1);
    m += __shfl_xor_sync(0xffffffffu, m, 2);
    m += __shfl_xor_sync(0xffffffffu, m, 4);
    m *= (1.f/128.f);
    float var = 0.f;
#pragma unroll
    for (int j = 0; j < 16; j++){ float d = v[j] - m; var += d*d; }
    var += __shfl_xor_sync(0xffffffffu, var, 1);
    var += __shfl_xor_sync(0xffffffffu, var, 2);
    var += __shfl_xor_sync(0xffffffffu, var, 4);
    var *= (1.f/128.f);
    const float rstd = rsqrtf(var + 1e-5f);
    float s0 = 0.f, s1 = 0.f;
#pragma unroll
    for (int j = 0; j < 16; j++){
        const int ch = j*8 + g;
        float o = (v[j] - m)*rstd*lnws[ch] + lnbs[ch];
        o = 0.5f * o * (1.f + erff(o * 0.70710678118654752440f));
        s0 += o * pws[ch];
        s1 += o * pws[128 + ch];
    }
    s0 += __shfl_xor_sync(0xffffffffu, s0, 1);
    s0 += __shfl_xor_sync(0xffffffffu, s0, 2);
    s0 += __shfl_xor_sync(0xffffffffu, s0, 4);
    s1 += __shfl_xor_sync(0xffffffffu, s1, 1);
    s1 += __shfl_xor_sync(0xffffffffu, s1, 2);
    s1 += __shfl_xor_sync(0xffffffffu, s1, 4);

    if (g == 0){
        float ry = ((y+0.5f)/31.f)*2.f - 1.f;
        float rx = ((x+0.5f)/31.f)*2.f - 1.f;
        float py = fminf(fmaxf(s0 + ry, -1.f), 1.f);
        float px = fminf(fmaxf(s1 + rx, -1.f), 1.f);
        int idx = (bg*Npts + y*32 + x)*2;
        g_pos[idx+0] = py;
        g_pos[idx+1] = px;
        if (write_pr){
            posref[idx+0] = py;
            posref[idx+1] = px;
            posref[Bn*Gn*Npts*2 + idx + 0] = ry;
            posref[Bn*Gn*Npts*2 + idx + 1] = rx;
        }
    }
}

// ---------------------------------------------------------------------------
__global__ __launch_bounds__(256) void sample_kernel(const float* __restrict__ x)
{
    const int cc = blockIdx.x;
    const int bg = blockIdx.y;
    const int b = bg >> 2, g = bg & 3;
    for (int n = threadIdx.x; n < Npts; n += 256){
        float py = g_pos[(bg*Npts+n)*2+0];
        float px = g_pos[(bg*Npts+n)*2+1];
        float gx = (px+1.f)*0.5f*31.f;
        float gy = (py+1.f)*0.5f*31.f;
        float x0f = floorf(gx), y0f = floorf(gy);
        float wx = gx-x0f, wy = gy-y0f;
        int x0 = max(min((int)x0f, 31), 0);
        int y0 = max(min((int)y0f, 31), 0);
        int x1 = min(x0+1, 31);
        int y1 = min(y0+1, 31);
        float w00 = (1.f-wx)*(1.f-wy), w10 = wx*(1.f-wy);
        float w01 = (1.f-wx)*wy,       w11 = wx*wy;
        for (int cj = 0; cj < 16; cj++){
            int cfull = g*GC + cc*16 + cj;
            const float* pl = x + ((size_t)(b*Cch + cfull))*HW;
            float val = pl[y0*32+x0]*w00 + pl[y0*32+x1]*w10
                      + pl[y1*32+x0]*w01 + pl[y1*32+x1]*w11;
            g_xs[((size_t)(b*Cch + cfull))*Npts + n] = val;
        }
    }
}

// ---------------------------------------------------------------------------
// Fused attention v5: m-tile 128, 8 warps (one per 16 rows x all 64 n).
// Register-only softmax state; separable RPE bias (per-n precompute);
// bf16 split output written directly to g_xth/g_xtl for the O GEMM.
// Dyn smem: 16640 + 1280 + 37888 + 37888 = 93696 B.
// ---------------------------------------------------------------------------
__global__ __launch_bounds__(256) void attn_kernel(const float* __restrict__ rpe)
{
    extern __shared__ char smraw[];
    float* rpe_s = (float*)smraw;                 // 4160 (64x64 zero-padded +64)
    float* w00_s = rpe_s + 4160;                  // 64
    float* w01_s = w00_s + 64;
    float* w10_s = w01_s + 64;
    float* w11_s = w10_s + 64;
    int*   nb_s  = (int*)(w11_s + 64);            // 64
    __nv_bfloat16* qh = (__nv_bfloat16*)(nb_s + 64);
    __nv_bfloat16* ql = qh + 128*74;
    __nv_bfloat16* kh = ql + 128*74;
    __nv_bfloat16* kl = kh + 64*74;
    __nv_bfloat16* vh = kl + 64*74;
    __nv_bfloat16* vl = vh + 64*74;

    const int tid = threadIdx.x;
    const int bh = blockIdx.y;
    const int m0 = blockIdx.x * 128;
    const int b = bh >> 3, h = bh & 7, gg = h >> 1;
    const int lane = tid & 31, wid = tid >> 5;
    const int g = lane >> 2, q4 = lane & 3;
    const int bg = b*Gn + gg;

    // rpe: 63x63 valid, stride 64, zero pad (row/col 63 and beyond)
    const float* rh = rpe + (size_t)h*RS*RS;
    for (int i = tid; i < 4160; i += 256){
        int row = i >> 6, col = i & 63;
        rpe_s[i] = (row < 63 && col < 63) ? rh[row*63 + col] : 0.f;
    }

    // Q load + split
    const float* qb = g_q + ((size_t)(b*Cch + h*HC))*HW + m0;
    for (int i = tid; i < 64*128; i += 256){
        int c = i >> 7, m = i & 127;
        float qv = qb[(size_t)c*HW + m];
        __nv_bfloat16 hi = __float2bfloat16(qv);
        qh[m*74 + c] = hi;
        ql[m*74 + c] = __float2bfloat16(qv - __bfloat162float(hi));
    }

    const int r0 = wid*16 + g, r1 = r0 + 8;
    const int mg0 = m0 + r0, mg1 = m0 + r1;
    const int mb0 = ((mg0 >> 5) << 6) + (mg0 & 31);
    const int mb1 = ((mg1 >> 5) << 6) + (mg1 & 31);

    const float* kb = g_k + ((size_t)(b*Cch + h*HC))*Npts;
    const float* vb = g_v + ((size_t)(b*Cch + h*HC))*Npts;

    float M0 = -1e30f, M1 = -1e30f, L0 = 0.f, L1 = 0.f;
    float oacc[8][4];
#pragma unroll
    for (int fc=0; fc<8; fc++)
#pragma unroll
        for (int e=0; e<4; e++) oacc[fc][e] = 0.f;

    for (int t = 0; t < 16; t++){
        // K/V load + split; per-n bias precompute
        for (int i = tid; i < 64*64; i += 256){
            int c = i >> 6, n = i & 63;
            float kv = kb[(size_t)c*Npts + t*64 + n];
            __nv_bfloat16 hk = __float2bfloat16(kv);
            kh[n*74 + c] = hk;
            kl[n*74 + c] = __float2bfloat16(kv - __bfloat162float(hk));
            float vv = vb[(size_t)c*Npts + t*64 + n];
            __nv_bfloat16 hv = __float2bfloat16(vv);
            vh[c*74 + n] = hv;
            vl[c*74 + n] = __float2bfloat16(vv - __bfloat162float(hv));
        }
        if (tid < 64){
            float py = g_pos[((size_t)bg*Npts + t*64 + tid)*2 + 0];
            float px = g_pos[((size_t)bg*Npts + t*64 + tid)*2 + 1];
            float cx = 15.5f*(1.f - px);
            float cy = 15.5f*(1.f - py);
            float fx = floorf(cx), fy = floorf(cy);
            float wx = cx - fx, wy = cy - fy;
            nb_s[tid] = ((int)fy)*64 + (int)fx;
            w00_s[tid] = (1.f-wx)*(1.f-wy);
            w01_s[tid] = wx*(1.f-wy);
            w10_s[tid] = (1.f-wx)*wy;
            w11_s[tid] = wx*wy;
        }
        __syncthreads();

        // ---- QK^T (bf16x3): warp covers m16 (r0,r1) x n64 ----
        float s[8][4];
#pragma unroll
        for (int fb=0; fb<8; fb++)
#pragma unroll
            for (int e=0; e<4; e++) s[fb][e] = 0.f;
#pragma unroll
        for (int ck = 0; ck < 4; ck++){
            const int a0 = r0*74 + ck*16 + 2*q4;
            const int a1 = r1*74 + ck*16 + 2*q4;
            uint32_t aH[4], aL[4];
            aH[0] = *(const uint32_t*)&qh[a0];   aH[1] = *(const uint32_t*)&qh[a1];
            aH[2] = *(const uint32_t*)&qh[a0+8]; aH[3] = *(const uint32_t*)&qh[a1+8];
            aL[0] = *(const uint32_t*)&ql[a0];   aL[1] = *(const uint32_t*)&ql[a1];
            aL[2] = *(const uint32_t*)&ql[a0+8]; aL[3] = *(const uint32_t*)&ql[a1+8];
#pragma unroll
            for (int fb = 0; fb < 8; fb++){
                const int kbse = (fb*8 + g)*74 + ck*16 + 2*q4;
                uint32_t bH0 = *(const uint32_t*)&kh[kbse];
                uint32_t bH1 = *(const uint32_t*)&kh[kbse+8];
                uint32_t bL0 = *(const uint32_t*)&kl[kbse];
                uint32_t bL1 = *(const uint32_t*)&kl[kbse+8];
                MMA_BF16(s[fb], aH[0],aH[1],aH[2],aH[3], bH0,bH1);
                MMA_BF16(s[fb], aH[0],aH[1],aH[2],aH[3], bL0,bL1);
                MMA_BF16(s[fb], aL[0],aL[1],aL[2],aL[3], bH0,bH1);
            }
        }

        // ---- scale + separable RPE bias ----
#pragma unroll
        for (int fb=0; fb<8; fb++){
#pragma unroll
            for (int j=0; j<2; j++){
                const int nl = fb*8 + 2*q4 + j;
                const int nb = nb_s[nl];
                const float w00 = w00_s[nl], w01 = w01_s[nl];
                const float w10 = w10_s[nl], w11 = w11_s[nl];
                {
                    const int base = mb0 + nb;
                    float bias = w00*rpe_s[base] + w01*rpe_s[base+1]
                               + w10*rpe_s[base+64] + w11*rpe_s[base+65];
                    s[fb][j] = s[fb][j]*0.125f + bias;
                }
                {
                    const int base = mb1 + nb;
                    float bias = w00*rpe_s[base] + w01*rpe_s[base+1]
                               + w10*rpe_s[base+64] + w11*rpe_s[base+65];
                    s[fb][2+j] = s[fb][2+j]*0.125f + bias;
                }
            }
        }

        // ---- register-only online softmax ----
        float mx0 = -1e30f, mx1 = -1e30f;
#pragma unroll
        for (int fb=0; fb<8; fb++){
            mx0 = fmaxf(mx0, fmaxf(s[fb][0], s[fb][1]));
            mx1 = fmaxf(mx1, fmaxf(s[fb][2], s[fb][3]));
        }
        mx0 = fmaxf(mx0, __shfl_xor_sync(0xffffffffu, mx0, 1));
        mx0 = fmaxf(mx0, __shfl_xor_sync(0xffffffffu, mx0, 2));
        mx1 = fmaxf(mx1, __shfl_xor_sync(0xffffffffu, mx1, 1));
        mx1 = fmaxf(mx1, __shfl_xor_sync(0xffffffffu, mx1, 2));
        const float Mn0 = fmaxf(M0, mx0), Mn1 = fmaxf(M1, mx1);
        const float al0 = __expf(M0 - Mn0), al1 = __expf(M1 - Mn1);
        M0 = Mn0; M1 = Mn1;

        float sum0 = 0.f, sum1 = 0.f;
#pragma unroll
        for (int fb=0; fb<8; fb++){
            s[fb][0] = __expf(s[fb][0] - Mn0); sum0 += s[fb][0];
            s[fb][1] = __expf(s[fb][1] - Mn0); sum0 += s[fb][1];
            s[fb][2] = __expf(s[fb][2] - Mn1); sum1 += s[fb][2];
            s[fb][3] = __expf(s[fb][3] - Mn1); sum1 += s[fb][3];
        }
        sum0 += __shfl_xor_sync(0xffffffffu, sum0, 1);
        sum0 += __shfl_xor_sync(0xffffffffu, sum0, 2);
        sum1 += __shfl_xor_sync(0xffffffffu, sum1, 1);
        sum1 += __shfl_xor_sync(0xffffffffu, sum1, 2);
        L0 = L0*al0 + sum0;
        L1 = L1*al1 + sum1;

#pragma unroll
        for (int fc=0; fc<8; fc++){
            oacc[fc][0] *= al0; oacc[fc][1] *= al0;
            oacc[fc][2] *= al1; oacc[fc][3] *= al1;
        }

        // ---- PV (bf16x3), k split over 4 chunks of n16 ----
#pragma unroll
        for (int ka = 0; ka < 4; ka++){
            uint32_t pH[4], pL[4];
            {
                float a = s[2*ka][0],  bb = s[2*ka][1];
                float c = s[2*ka][2],  d  = s[2*ka][3];
                float e = s[2*ka+1][0],f  = s[2*ka+1][1];
                float gv = s[2*ka+1][2],hh = s[2*ka+1][3];
                float ah_ = __bfloat162float(__float2bfloat16(a));
                float bh_ = __bfloat162float(__float2bfloat16(bb));
                float ch_ = __bfloat162float(__float2bfloat16(c));
                float dh_ = __bfloat162float(__float2bfloat16(d));
                float eh_ = __bfloat162float(__float2bfloat16(e));
                float fh_ = __bfloat162float(__float2bfloat16(f));
                float gh_ = __bfloat162float(__float2bfloat16(gv));
                float hh_ = __bfloat162float(__float2bfloat16(hh));
                pH[0] = packbf(ah_, bh_); pH[1] = packbf(ch_, dh_);
                pH[2] = packbf(eh_, fh_); pH[3] = packbf(gh_, hh_);
                pL[0] = packbf(a-ah_, bb-bh_); pL[1] = packbf(c-ch_, d-dh_);
                pL[2] = packbf(e-eh_, f-fh_);  pL[3] = packbf(gv-gh_, hh-hh_);
            }
            const int nb = ka*16;
#pragma unroll
            for (int fc = 0; fc < 8; fc++){
                const int vbse = (fc*8 + g)*74 + nb + 2*q4;
                uint32_t vH0 = *(const uint32_t*)&vh[vbse];
                uint32_t vH1 = *(const uint32_t*)&vh[vbse+8];
                uint32_t vL0 = *(const uint32_t*)&vl[vbse];
                uint32_t vL1 = *(const uint32_t*)&vl[vbse+8];
                MMA_BF16(oacc[fc], pH[0],pH[1],pH[2],pH[3], vH0,vH1);
                MMA_BF16(oacc[fc], pH[0],pH[1],pH[2],pH[3], vL0,vL1);
                MMA_BF16(oacc[fc], pL[0],pL[1],pL[2],pL[3], vH0,vH1);
            }
        }
        __syncthreads();
    }

    // epilogue: normalize + bf16 split, write [m][c] for O GEMM
    const float rl0 = 1.f / L0, rl1 = 1.f / L1;
    const size_t base0 = ((size_t)(b*HW) + mg0)*Cch + h*HC;
    const size_t base1 = ((size_t)(b*HW) + mg1)*Cch + h*HC;
#pragma unroll
    for (int fc = 0; fc < 8; fc++){
        const int c0 = fc*8 + 2*q4;
        float v00 = oacc[fc][0]*rl0, v01 = oacc[fc][1]*rl0;
        float v10 = oacc[fc][2]*rl1, v11 = oacc[fc][3]*rl1;
        float h00 = __bfloat162float(__float2bfloat16(v00));
        float h01 = __bfloat162float(__float2bfloat16(v01));
        float h10 = __bfloat162float(__float2bfloat16(v10));
        float h11 = __bfloat162float(__float2bfloat16(v11));
        *(uint32_t*)&g_xth[base0 + c0] = packbf(h00, h01);
        *(uint32_t*)&g_xtl[base0 + c0] = packbf(v00-h00, v01-h01);
        *(uint32_t*)&g_xth[base1 + c0] = packbf(h10, h11);
        *(uint32_t*)&g_xtl[base1 + c0] = packbf(v10-h10, v11-h11);
    }
}

// ---------------------------------------------------------------------------
extern "C" void kernel_launch(void* const* d_in, const int* in_sizes, int n_in,
                              void* d_out, int out_size)
{
    const float* x   = (const float*)d_in[0];
    const float* wq  = (const float*)d_in[1];
    const float* bq  = (const float*)d_in[2];
    const float* wk  = (const float*)d_in[3];
    const float* bk  = (const float*)d_in[4];
    const float* wv  = (const float*)d_in[5];
    const float* bv  = (const float*)d_in[6];
    const float* wo  = (const float*)d_in[7];
    const float* bo  = (const float*)d_in[8];
    const float* dww = (const float*)d_in[9];
    const float* dwb = (const float*)d_in[10];
    const float* lnw = (const float*)d_in[11];
    const float* lnb = (const float*)d_in[12];
    const float* pww = (const float*)d_in[13];
    const float* rpe = (const float*)d_in[14];
    float* out = (float*)d_out;

    void *pq, *pxs, *pk, *pv, *pwh, *pwl;
    cudaGetSymbolAddress(&pq,  g_q);
    cudaGetSymbolAddress(&pxs, g_xs);
    cudaGetSymbolAddress(&pk,  g_k);
    cudaGetSymbolAddress(&pv,  g_v);
    cudaGetSymbolAddress(&pwh, g_wh);
    cudaGetSymbolAddress(&pwl, g_wl);
    cudaFuncSetAttribute(attn_kernel, cudaFuncAttributeMaxDynamicSharedMemorySize, 93696);
    cudaFuncSetAttribute(offset_kernel, cudaFuncAttributeMaxDynamicSharedMemorySize, 59392);

    const __nv_bfloat16* wh = (const __nv_bfloat16*)pwh;
    const __nv_bfloat16* wl = (const __nv_bfloat16*)pwl;

    const int write_pr = (out_size >= Bn*Cch*HW + 2*Bn*Gn*Npts*2) ? 1 : 0;
    float* posref = out + Bn*Cch*HW;

    const dim3 gmm(HW/128, Cch/128, Bn);
    const dim3 gtr(HW/32, Cch/32, Bn);

    convert_w<<<dim3(Cch*Cch/256, 4), 256>>>(wq, wk, wv, wo);
    trans_conv<<<gtr, 256>>>(x);
    gemm_mma<<<gmm, 256>>>(wh + 0*Cch*Cch, wl + 0*Cch*Cch, bq, (float*)pq);
    offset_kernel<<<dim3(32, Bn*Gn), 256, 59392>>>(dww, dwb, lnw, lnb, pww, posref, write_pr);
    sample_kernel<<<dim3(8, Bn*Gn), 256>>>(x);
    trans_conv<<<gtr, 256>>>((const float*)pxs);
    gemm_mma<<<gmm, 256>>>(wh + 1*Cch*Cch, wl + 1*Cch*Cch, bk, (float*)pk);
    gemm_mma<<<gmm, 256>>>(wh + 2*Cch*Cch, wl + 2*Cch*Cch, bv, (float*)pv);
    attn_kernel<<<dim3(HW/128, Bn*HEADS), 256, 93696>>>(rpe);
    gemm_mma<<<gmm, 256>>>(wh + 3*Cch*Cch, wl + 3*Cch*Cch, bo, out);
}